// round 3
// baseline (speedup 1.0000x reference)
#include <cuda_runtime.h>
#include <stdint.h>

#define WIN   442
#define NBINS 221
#define HOP   4
#define RELC  0.0594f
#define CWIN  128           // windows per DFT block
#define SEG   2048          // windows per scan segment
#define MAXWIN 262144
#define MAXSEG (MAXWIN / SEG)

__device__ float g_ct_hi[WIN];
__device__ float g_ct_lo[WIN];
__device__ float g_st_hi[WIN];
__device__ float g_st_lo[WIN];
__device__ int   g_bins[MAXWIN];
__device__ int2  g_maps[MAXSEG * NBINS];
__device__ int2  g_segin[MAXSEG];

// ---------------------------------------------------------------------------
// Twiddle tables: cos/sin(2*pi*m/442) as double-float (hi, lo) pairs.
// ---------------------------------------------------------------------------
__global__ void k_init_tables() {
    int m = threadIdx.x;
    if (m < WIN) {
        double ang = (2.0 * 3.141592653589793238462643 * (double)m) / (double)WIN;
        double c = cos(ang), s = sin(ang);
        float ch = (float)c, sh = (float)s;
        g_ct_hi[m] = ch; g_ct_lo[m] = (float)(c - (double)ch);
        g_st_hi[m] = sh; g_st_lo[m] = (float)(s - (double)sh);
    }
}

// exact two-sum (Knuth); all rounding via explicit intrinsics so the
// compiler cannot contract/reassociate.
__device__ __forceinline__ float2 two_sum(float a, float b) {
    float s  = __fadd_rn(a, b);
    float bp = __fsub_rn(s, a);
    float e  = __fadd_rn(__fsub_rn(a, __fsub_rn(s, bp)), __fsub_rn(b, bp));
    return make_float2(s, e);
}

// ---------------------------------------------------------------------------
// DFT + argmax. One block = 128 consecutive windows, thread k = bin k.
// First window: direct 442-tap DFT with compensated (hi,lo) accumulation.
// Remaining 127: hop-4 sliding update; additive deltas in fp32 fma (small),
// rotation by w4 carried out in double-float with double-split twiddles so
// no multiplicative drift accumulates across the chunk.
// Per window: warp max-reduce of key = (mag_bits<<32) | ~bin (ties -> lowest
// bin, matching jnp.argmax).
// ---------------------------------------------------------------------------
__global__ __launch_bounds__(224) void k_dft(const float* __restrict__ x, int n_win) {
    __shared__ float xs[WIN + 4 * CWIN];     // 954 samples
    __shared__ float ct[WIN], st[WIN];
    __shared__ unsigned long long wk[CWIN][7];

    const int tid = threadIdx.x;
    const int w0  = blockIdx.x * CWIN;
    const int nc  = min(CWIN, n_win - w0);
    const int s0  = w0 * HOP;
    const int L   = 4 * nc + 438;            // samples this chunk needs

    for (int i = tid; i < L; i += blockDim.x)  xs[i] = x[s0 + i];
    for (int i = tid; i < WIN; i += blockDim.x) { ct[i] = g_ct_hi[i]; st[i] = g_st_hi[i]; }
    __syncthreads();

    const int k    = tid;
    const int lane = tid & 31;
    const int wid  = tid >> 5;
    const bool act = (k < NBINS);

    // per-bin twiddles for the slide update (hi only; error non-accumulating)
    float c1 = 0.f, s1 = 0.f, c2 = 0.f, s2 = 0.f, c3 = 0.f, s3 = 0.f;
    // rotation twiddle w4 = e^{+i 2pi 4k/442} as double-float
    float w4ch = 1.f, w4cl = 0.f, w4sh = 0.f, w4sl = 0.f;
    if (act) {
        c1 = ct[k];      s1 = st[k];
        c2 = ct[2 * k];  s2 = st[2 * k];            // 2k <= 440 < 442
        int i3 = 3 * k;  if (i3 >= WIN) i3 -= WIN;
        c3 = ct[i3];     s3 = st[i3];
        int i4 = 4 * k;  if (i4 >= WIN) i4 -= WIN;
        w4ch = g_ct_hi[i4]; w4cl = g_ct_lo[i4];
        w4sh = g_st_hi[i4]; w4sl = g_st_lo[i4];
    }

    // direct DFT of first window with compensated accumulation:
    // X[k] = sum x_n (cos - i sin)
    float re_hi = 0.f, re_lo = 0.f, im_hi = 0.f, im_lo = 0.f;
    if (act) {
        int idx = 0;
        #pragma unroll 2
        for (int nn = 0; nn < WIN; nn++) {
            float xv = xs[nn];
            float pr = __fmul_rn(xv, ct[idx]);
            float pi = __fmul_rn(xv, st[idx]);
            float2 tr = two_sum(re_hi, pr);
            re_hi = tr.x; re_lo = __fadd_rn(re_lo, tr.y);
            float2 ti = two_sum(im_hi, pi);
            im_hi = ti.x; im_lo = __fadd_rn(im_lo, ti.y);
            idx += k; if (idx >= WIN) idx -= WIN;
        }
        im_hi = -im_hi; im_lo = -im_lo;
    }

    for (int w = 0; w < nc; w++) {
        float rv = __fadd_rn(re_hi, re_lo);
        float iv = __fadd_rn(im_hi, im_lo);
        float mag = __fadd_rn(fabsf(rv), fabsf(iv));
        unsigned long long key = act
            ? (((unsigned long long)__float_as_uint(mag) << 32)
               | (unsigned long long)(0xFFFFFFFFu - (unsigned)k))
            : 0ull;
        #pragma unroll
        for (int o = 16; o > 0; o >>= 1) {
            unsigned long long other = __shfl_xor_sync(0xffffffffu, key, o);
            if (other > key) key = other;
        }
        if (lane == 0) wk[w][wid] = key;

        if (w + 1 < nc && act) {
            int p = 4 * w;
            float d0 = __fsub_rn(xs[p + 442], xs[p]);
            float d1 = __fsub_rn(xs[p + 443], xs[p + 1]);
            float d2 = __fsub_rn(xs[p + 444], xs[p + 2]);
            float d3 = __fsub_rn(xs[p + 445], xs[p + 3]);

            // additive deltas (fp32; error relative to |X| is ~5e-8 total)
            float dre = d0;
            dre = __fmaf_rn(d1, c1, dre);
            dre = __fmaf_rn(d2, c2, dre);
            dre = __fmaf_rn(d3, c3, dre);
            float dim = __fmul_rn(-d1, s1);
            dim = __fmaf_rn(-d2, s2, dim);
            dim = __fmaf_rn(-d3, s3, dim);

            // ar = re + dre  (exact fold into hi,lo; no renorm needed)
            float2 t;
            t = two_sum(re_hi, dre);
            float ar_hi = t.x, ar_lo = __fadd_rn(re_lo, t.y);
            t = two_sum(im_hi, dim);
            float ai_hi = t.x, ai_lo = __fadd_rn(im_lo, t.y);

            // double-float rotation: re' = ar*w4c - ai*w4s ; im' = ar*w4s + ai*w4c
            // p = ar (x) w4c
            float p_hi = __fmul_rn(ar_hi, w4ch);
            float p_lo = __fmaf_rn(ar_hi, w4ch, -p_hi);
            p_lo = __fmaf_rn(ar_hi, w4cl, p_lo);
            p_lo = __fmaf_rn(ar_lo, w4ch, p_lo);
            // q = ai (x) w4s
            float q_hi = __fmul_rn(ai_hi, w4sh);
            float q_lo = __fmaf_rn(ai_hi, w4sh, -q_hi);
            q_lo = __fmaf_rn(ai_hi, w4sl, q_lo);
            q_lo = __fmaf_rn(ai_lo, w4sh, q_lo);
            // r = ar (x) w4s
            float r_hi = __fmul_rn(ar_hi, w4sh);
            float r_lo = __fmaf_rn(ar_hi, w4sh, -r_hi);
            r_lo = __fmaf_rn(ar_hi, w4sl, r_lo);
            r_lo = __fmaf_rn(ar_lo, w4sh, r_lo);
            // u = ai (x) w4c
            float u_hi = __fmul_rn(ai_hi, w4ch);
            float u_lo = __fmaf_rn(ai_hi, w4ch, -u_hi);
            u_lo = __fmaf_rn(ai_hi, w4cl, u_lo);
            u_lo = __fmaf_rn(ai_lo, w4ch, u_lo);

            // re' = p - q (two_sum on his, fold los, renormalize)
            t = two_sum(p_hi, -q_hi);
            float nlo = __fadd_rn(t.y, __fsub_rn(p_lo, q_lo));
            re_hi = __fadd_rn(t.x, nlo);
            re_lo = __fadd_rn(__fsub_rn(t.x, re_hi), nlo);
            // im' = r + u
            t = two_sum(r_hi, u_hi);
            nlo = __fadd_rn(t.y, __fadd_rn(r_lo, u_lo));
            im_hi = __fadd_rn(t.x, nlo);
            im_lo = __fadd_rn(__fsub_rn(t.x, im_hi), nlo);
        }
    }
    __syncthreads();

    if (tid < nc) {
        unsigned long long m = wk[tid][0];
        #pragma unroll
        for (int j = 1; j < 7; j++) if (wk[tid][j] > m) m = wk[tid][j];
        g_bins[w0 + tid] = (int)(0xFFFFFFFFu - (unsigned)(m & 0xFFFFFFFFull));
    }
}

// ---------------------------------------------------------------------------
// Scan phase 1: per-segment transition maps. State F is always bin*100
// (221 possible values; initial F=0 == bin 0, identical semantics).
// ---------------------------------------------------------------------------
__global__ void k_segmaps(int n_win) {
    __shared__ int   sb[SEG];
    __shared__ short sj[SEG];
    const int seg = blockIdx.x;
    const int s0  = seg * SEG;
    const int len = min(SEG, n_win - s0);

    for (int i = threadIdx.x; i < SEG; i += blockDim.x)
        sb[i] = (i < len) ? g_bins[s0 + i] : 0;
    __syncthreads();

    for (int p = threadIdx.x; p < len; p += blockDim.x) {
        float F   = 100.0f * (float)sb[p];
        float thr = F * RELC;
        int j = p + 1;
        while (j < len && fabsf(F - 100.0f * (float)sb[j]) <= thr) j++;
        sj[p] = (short)((j < len) ? j : p);      // self-loop == terminal
    }
    __syncthreads();

    for (int r = 0; r < 11; r++) {               // log2(2048) rounds
        for (int p = threadIdx.x; p < len; p += blockDim.x)
            sj[p] = sj[sj[p]];
        __syncthreads();
    }

    for (int f = threadIdx.x; f < NBINS; f += blockDim.x) {
        float F   = 100.0f * (float)f;
        float thr = F * RELC;
        int j = 0;
        while (j < len && fabsf(F - 100.0f * (float)sb[j]) <= thr) j++;
        int2 m;
        if (j >= len) { m.x = f; m.y = -1; }
        else { int term = sj[j]; m.x = sb[term]; m.y = s0 + term; }
        g_maps[seg * NBINS + f] = m;
    }
}

// ---------------------------------------------------------------------------
// Scan phase 2: sequential walk over ~123 segment maps.
// ---------------------------------------------------------------------------
__global__ void k_walk(int n_win, int nseg, float* __restrict__ out) {
    int bF = 0, Tw = 0;
    for (int s = 0; s < nseg; s++) {
        g_segin[s] = make_int2(bF, Tw);
        int2 m = g_maps[s * NBINS + bF];
        if (m.y >= 0) { bF = m.x; Tw = m.y; }
    }
    float F    = 100.0f * (float)bF;
    float Ft   = 4.0f * (float)Tw;
    float last = 4.0f * (float)(n_win - 1);
    out[3 * n_win + 0] = F;
    out[3 * n_win + 1] = __fdiv_rn((last - Ft) * 1000.0f, 44100.0f);
}

// ---------------------------------------------------------------------------
// Scan phase 3: parallel fill. One warp per segment replays the exact
// reference emit semantics (cond/emit use PRE-update state) via ballots.
// ---------------------------------------------------------------------------
__global__ void k_fill(int n_win, float* __restrict__ out) {
    const int seg = blockIdx.x;
    const int s0  = seg * SEG;
    const int len = min(SEG, n_win - s0);
    const int lane = threadIdx.x;

    int2 st0 = g_segin[seg];
    float F = 100.0f * (float)st0.x;
    float T = 4.0f * (float)st0.y;

    float* flags = out;
    float* freqs = out + n_win;
    float* durs  = out + 2 * n_win;

    for (int base = 0; base < len; base += 32) {
        int  i     = s0 + base + lane;
        bool valid = (base + lane) < len;
        float t = valid ? 100.0f * (float)g_bins[i] : 0.0f;

        unsigned rem = __ballot_sync(0xffffffffu, valid);
        float myF = 0.f, myT = 0.f;
        bool  myc = false;
        while (rem) {
            bool oob = fabsf(F - t) > F * RELC;
            unsigned bal = __ballot_sync(0xffffffffu, oob) & rem;
            if (!bal) {
                if (rem & (1u << lane)) { myF = F; myT = T; }
                break;
            }
            int e = __ffs(bal) - 1;
            if ((rem & (1u << lane)) && lane <= e) {
                myF = F; myT = T; myc = (lane == e);
            }
            F = __shfl_sync(0xffffffffu, t, e);
            T = 4.0f * (float)(s0 + base + e);
            unsigned below = (e == 31) ? 0xffffffffu : ((1u << (e + 1)) - 1u);
            rem &= ~below;
        }
        if (valid) {
            flags[i] = myc ? 1.0f : 0.0f;
            freqs[i] = myF;
            durs[i]  = __fdiv_rn(((float)(4 * i) - myT) * 1000.0f, 44100.0f);
        }
    }
}

// ---------------------------------------------------------------------------
extern "C" void kernel_launch(void* const* d_in, const int* in_sizes, int n_in,
                              void* d_out, int out_size) {
    const float* x = (const float*)d_in[0];
    int n     = in_sizes[0];
    int n_win = (n - WIN + HOP - 1) / HOP;
    if (n_win > MAXWIN) n_win = MAXWIN;   // safety cap (fixed input: 249890)
    int nblk = (n_win + CWIN - 1) / CWIN;
    int nseg = (n_win + SEG - 1) / SEG;
    float* out = (float*)d_out;

    k_init_tables<<<1, 448>>>();
    k_dft<<<nblk, 224>>>(x, n_win);
    k_segmaps<<<nseg, 256>>>(n_win);
    k_walk<<<1, 1>>>(n_win, nseg, out);
    k_fill<<<nseg, 32>>>(n_win, out);
}

// round 4
// speedup vs baseline: 1.1536x; 1.1536x over previous
#include <cuda_runtime.h>
#include <stdint.h>

#define WIN   442
#define NBINS 221
#define HOP   4
#define RELC  0.0594f
#define CWIN  256           // windows per DFT block
#define SEG   2048          // windows per scan segment
#define MAXWIN 262144
#define MAXSEG (MAXWIN / SEG)

__device__ float g_ct_hi[WIN];
__device__ float g_ct_lo[WIN];
__device__ float g_st_hi[WIN];
__device__ float g_st_lo[WIN];
__device__ int   g_bins[MAXWIN];
__device__ int2  g_maps[MAXSEG * NBINS];
__device__ int2  g_segin[MAXSEG];

// ---------------------------------------------------------------------------
// Twiddle tables: cos/sin(2*pi*m/442) as double-float (hi, lo) pairs.
// ---------------------------------------------------------------------------
__global__ void k_init_tables() {
    int m = threadIdx.x;
    if (m < WIN) {
        double ang = (2.0 * 3.141592653589793238462643 * (double)m) / (double)WIN;
        double c = cos(ang), s = sin(ang);
        float ch = (float)c, sh = (float)s;
        g_ct_hi[m] = ch; g_ct_lo[m] = (float)(c - (double)ch);
        g_st_hi[m] = sh; g_st_lo[m] = (float)(s - (double)sh);
    }
}

// exact two-sum (Knuth); explicit intrinsics block contraction/reassociation.
__device__ __forceinline__ float2 two_sum(float a, float b) {
    float s  = __fadd_rn(a, b);
    float bp = __fsub_rn(s, a);
    float e  = __fadd_rn(__fsub_rn(a, __fsub_rn(s, bp)), __fsub_rn(b, bp));
    return make_float2(s, e);
}

// ---------------------------------------------------------------------------
// DFT + argmax. One block = 256 consecutive windows, thread k = bin k.
// First window: direct 442-tap DFT with compensated (hi,lo) accumulation.
// Remaining 255: hop-4 sliding update. Additive deltas folded into the lo
// word (cheap; dropped terms <= ~1e-8 |X| per step, random), rotation by w4
// done in double-float with double-split twiddles -> no accumulating drift.
// Per window: fp32 warp max + equality ballot (ties -> lowest bin, matching
// jnp.argmax), then cross-warp 64-bit key merge at the end.
// ---------------------------------------------------------------------------
__global__ __launch_bounds__(224) void k_dft(const float* __restrict__ x, int n_win) {
    __shared__ float xs[WIN + 4 * CWIN];     // 1466 samples
    __shared__ float ct[WIN], st[WIN];
    __shared__ unsigned long long wk[CWIN][7];

    const int tid = threadIdx.x;
    const int w0  = blockIdx.x * CWIN;
    const int nc  = min(CWIN, n_win - w0);
    const int s0  = w0 * HOP;
    const int L   = 4 * nc + 438;            // samples this chunk needs

    for (int i = tid; i < L; i += blockDim.x)  xs[i] = x[s0 + i];
    for (int i = tid; i < WIN; i += blockDim.x) { ct[i] = g_ct_hi[i]; st[i] = g_st_hi[i]; }
    __syncthreads();

    const int k    = tid;
    const int lane = tid & 31;
    const int wid  = tid >> 5;
    const bool act = (k < NBINS);

    // per-bin twiddles for the slide update (hi only; error non-accumulating)
    float c1 = 0.f, s1 = 0.f, c2 = 0.f, s2 = 0.f, c3 = 0.f, s3 = 0.f;
    // rotation twiddle w4 = e^{+i 2pi 4k/442} as double-float
    float w4ch = 1.f, w4cl = 0.f, w4sh = 0.f, w4sl = 0.f;
    if (act) {
        c1 = ct[k];      s1 = st[k];
        c2 = ct[2 * k];  s2 = st[2 * k];            // 2k <= 440 < 442
        int i3 = 3 * k;  if (i3 >= WIN) i3 -= WIN;
        c3 = ct[i3];     s3 = st[i3];
        int i4 = 4 * k;  if (i4 >= WIN) i4 -= WIN;
        w4ch = g_ct_hi[i4]; w4cl = g_ct_lo[i4];
        w4sh = g_st_hi[i4]; w4sl = g_st_lo[i4];
    }

    // direct DFT of first window with compensated accumulation:
    // X[k] = sum x_n (cos - i sin)
    float re_hi = 0.f, re_lo = 0.f, im_hi = 0.f, im_lo = 0.f;
    if (act) {
        int idx = 0;
        #pragma unroll 2
        for (int nn = 0; nn < WIN; nn++) {
            float xv = xs[nn];
            float pr = __fmul_rn(xv, ct[idx]);
            float pi = __fmul_rn(xv, st[idx]);
            float2 tr = two_sum(re_hi, pr);
            re_hi = tr.x; re_lo = __fadd_rn(re_lo, tr.y);
            float2 ti = two_sum(im_hi, pi);
            im_hi = ti.x; im_lo = __fadd_rn(im_lo, ti.y);
            idx += k; if (idx >= WIN) idx -= WIN;
        }
        im_hi = -im_hi; im_lo = -im_lo;
    }

    for (int w = 0; w < nc; w++) {
        // evaluate magnitude
        float rv  = __fadd_rn(re_hi, re_lo);
        float iv  = __fadd_rn(im_hi, im_lo);
        float mag = act ? __fadd_rn(fabsf(rv), fabsf(iv)) : -1.0f;

        // warp argmax: fp32 max-reduce + equality ballot (lowest lane wins)
        float mx = mag;
        #pragma unroll
        for (int o = 16; o > 0; o >>= 1)
            mx = fmaxf(mx, __shfl_xor_sync(0xffffffffu, mx, o));
        unsigned eq = __ballot_sync(0xffffffffu, mag == mx);
        if (lane == 0) {
            unsigned bin = (unsigned)(wid * 32 + (__ffs(eq) - 1));
            wk[w][wid] = (((unsigned long long)__float_as_uint(mx)) << 32)
                         | (unsigned long long)(0xFFFFFFFFu - bin);
        }

        if (w + 1 < nc && act) {
            int p = 4 * w;
            float d0 = __fsub_rn(xs[p + 442], xs[p]);
            float d1 = __fsub_rn(xs[p + 443], xs[p + 1]);
            float d2 = __fsub_rn(xs[p + 444], xs[p + 2]);
            float d3 = __fsub_rn(xs[p + 445], xs[p + 3]);

            float dre = d0;
            dre = __fmaf_rn(d1, c1, dre);
            dre = __fmaf_rn(d2, c2, dre);
            dre = __fmaf_rn(d3, c3, dre);
            float dim = __fmul_rn(-d1, s1);
            dim = __fmaf_rn(-d2, s2, dim);
            dim = __fmaf_rn(-d3, s3, dim);

            // fold deltas into the lo word only (analysis: safe to ~1e-8/step)
            float ar_hi = re_hi, ar_lo = __fadd_rn(re_lo, dre);
            float ai_hi = im_hi, ai_lo = __fadd_rn(im_lo, dim);

            // double-float rotation: re' = ar*w4c - ai*w4s ; im' = ar*w4s + ai*w4c
            float p_hi = __fmul_rn(ar_hi, w4ch);
            float p_lo = __fmaf_rn(ar_hi, w4ch, -p_hi);
            p_lo = __fmaf_rn(ar_hi, w4cl, p_lo);
            p_lo = __fmaf_rn(ar_lo, w4ch, p_lo);

            float q_hi = __fmul_rn(ai_hi, w4sh);
            float q_lo = __fmaf_rn(ai_hi, w4sh, -q_hi);
            q_lo = __fmaf_rn(ai_hi, w4sl, q_lo);
            q_lo = __fmaf_rn(ai_lo, w4sh, q_lo);

            float r_hi = __fmul_rn(ar_hi, w4sh);
            float r_lo = __fmaf_rn(ar_hi, w4sh, -r_hi);
            r_lo = __fmaf_rn(ar_hi, w4sl, r_lo);
            r_lo = __fmaf_rn(ar_lo, w4sh, r_lo);

            float u_hi = __fmul_rn(ai_hi, w4ch);
            float u_lo = __fmaf_rn(ai_hi, w4ch, -u_hi);
            u_lo = __fmaf_rn(ai_hi, w4cl, u_lo);
            u_lo = __fmaf_rn(ai_lo, w4ch, u_lo);

            float2 t;
            t = two_sum(p_hi, -q_hi);
            float nlo = __fadd_rn(t.y, __fsub_rn(p_lo, q_lo));
            re_hi = __fadd_rn(t.x, nlo);
            re_lo = __fadd_rn(__fsub_rn(t.x, re_hi), nlo);

            t = two_sum(r_hi, u_hi);
            nlo = __fadd_rn(t.y, __fadd_rn(r_lo, u_lo));
            im_hi = __fadd_rn(t.x, nlo);
            im_lo = __fadd_rn(__fsub_rn(t.x, im_hi), nlo);
        }
    }
    __syncthreads();

    for (int i = tid; i < nc; i += blockDim.x) {
        unsigned long long m = wk[i][0];
        #pragma unroll
        for (int j = 1; j < 7; j++) if (wk[i][j] > m) m = wk[i][j];
        g_bins[w0 + i] = (int)(0xFFFFFFFFu - (unsigned)(m & 0xFFFFFFFFull));
    }
}

// ---------------------------------------------------------------------------
// Scan phase 1: per-segment transition maps. State F is always bin*100
// (221 possible values; initial F=0 == bin 0, identical semantics).
// ---------------------------------------------------------------------------
__global__ void k_segmaps(int n_win) {
    __shared__ int   sb[SEG];
    __shared__ short sj[SEG];
    const int seg = blockIdx.x;
    const int s0  = seg * SEG;
    const int len = min(SEG, n_win - s0);

    for (int i = threadIdx.x; i < SEG; i += blockDim.x)
        sb[i] = (i < len) ? g_bins[s0 + i] : 0;
    __syncthreads();

    for (int p = threadIdx.x; p < len; p += blockDim.x) {
        float F   = 100.0f * (float)sb[p];
        float thr = F * RELC;
        int j = p + 1;
        while (j < len && fabsf(F - 100.0f * (float)sb[j]) <= thr) j++;
        sj[p] = (short)((j < len) ? j : p);      // self-loop == terminal
    }
    __syncthreads();

    for (int r = 0; r < 11; r++) {               // log2(2048) rounds
        for (int p = threadIdx.x; p < len; p += blockDim.x)
            sj[p] = sj[sj[p]];
        __syncthreads();
    }

    for (int f = threadIdx.x; f < NBINS; f += blockDim.x) {
        float F   = 100.0f * (float)f;
        float thr = F * RELC;
        int j = 0;
        while (j < len && fabsf(F - 100.0f * (float)sb[j]) <= thr) j++;
        int2 m;
        if (j >= len) { m.x = f; m.y = -1; }
        else { int term = sj[j]; m.x = sb[term]; m.y = s0 + term; }
        g_maps[seg * NBINS + f] = m;
    }
}

// ---------------------------------------------------------------------------
// Scan phase 2: bulk-load all segment maps into shared (packed 32-bit:
// time<<8 | bin, sentinel = 0xFFFFFFFF), then walk the dependency chain in
// shared memory (~30 cyc/step instead of ~450 cyc global-latency steps).
// ---------------------------------------------------------------------------
__global__ void k_walk(int n_win, int nseg, float* __restrict__ out) {
    extern __shared__ unsigned sm[];
    const int tot = nseg * NBINS;
    for (int i = threadIdx.x; i < tot; i += blockDim.x) {
        int2 m = g_maps[i];
        sm[i] = (m.y < 0) ? 0xFFFFFFFFu : (((unsigned)m.y << 8) | (unsigned)m.x);
    }
    __syncthreads();

    if (threadIdx.x == 0) {
        int bF = 0, Tw = 0;
        for (int s = 0; s < nseg; s++) {
            g_segin[s] = make_int2(bF, Tw);
            unsigned v = sm[s * NBINS + bF];
            if (v != 0xFFFFFFFFu) { bF = (int)(v & 0xFFu); Tw = (int)(v >> 8); }
        }
        float F    = 100.0f * (float)bF;
        float Ft   = 4.0f * (float)Tw;
        float last = 4.0f * (float)(n_win - 1);
        out[3 * n_win + 0] = F;
        out[3 * n_win + 1] = __fdiv_rn((last - Ft) * 1000.0f, 44100.0f);
    }
}

// ---------------------------------------------------------------------------
// Scan phase 3: parallel fill. One warp per segment replays the exact
// reference emit semantics (cond/emit use PRE-update state) via ballots.
// ---------------------------------------------------------------------------
__global__ void k_fill(int n_win, float* __restrict__ out) {
    const int seg = blockIdx.x;
    const int s0  = seg * SEG;
    const int len = min(SEG, n_win - s0);
    const int lane = threadIdx.x;

    int2 st0 = g_segin[seg];
    float F = 100.0f * (float)st0.x;
    float T = 4.0f * (float)st0.y;

    float* flags = out;
    float* freqs = out + n_win;
    float* durs  = out + 2 * n_win;

    for (int base = 0; base < len; base += 32) {
        int  i     = s0 + base + lane;
        bool valid = (base + lane) < len;
        float t = valid ? 100.0f * (float)g_bins[i] : 0.0f;

        unsigned rem = __ballot_sync(0xffffffffu, valid);
        float myF = 0.f, myT = 0.f;
        bool  myc = false;
        while (rem) {
            bool oob = fabsf(F - t) > F * RELC;
            unsigned bal = __ballot_sync(0xffffffffu, oob) & rem;
            if (!bal) {
                if (rem & (1u << lane)) { myF = F; myT = T; }
                break;
            }
            int e = __ffs(bal) - 1;
            if ((rem & (1u << lane)) && lane <= e) {
                myF = F; myT = T; myc = (lane == e);
            }
            F = __shfl_sync(0xffffffffu, t, e);
            T = 4.0f * (float)(s0 + base + e);
            unsigned below = (e == 31) ? 0xffffffffu : ((1u << (e + 1)) - 1u);
            rem &= ~below;
        }
        if (valid) {
            flags[i] = myc ? 1.0f : 0.0f;
            freqs[i] = myF;
            durs[i]  = __fdiv_rn(((float)(4 * i) - myT) * 1000.0f, 44100.0f);
        }
    }
}

// ---------------------------------------------------------------------------
extern "C" void kernel_launch(void* const* d_in, const int* in_sizes, int n_in,
                              void* d_out, int out_size) {
    const float* x = (const float*)d_in[0];
    int n     = in_sizes[0];
    int n_win = (n - WIN + HOP - 1) / HOP;
    if (n_win > MAXWIN) n_win = MAXWIN;   // safety cap (fixed input: 249890)
    int nblk = (n_win + CWIN - 1) / CWIN;
    int nseg = (n_win + SEG - 1) / SEG;
    float* out = (float*)d_out;

    size_t walk_smem = (size_t)nseg * NBINS * sizeof(unsigned);  // ~108.7 KB
    static bool attr_done = false;
    if (!attr_done) {
        cudaFuncSetAttribute(k_walk, cudaFuncAttributeMaxDynamicSharedMemorySize,
                             (int)(112 * 1024));
        attr_done = true;
    }

    k_init_tables<<<1, 448>>>();
    k_dft<<<nblk, 224>>>(x, n_win);
    k_segmaps<<<nseg, 256>>>(n_win);
    k_walk<<<1, 512, walk_smem>>>(n_win, nseg, out);
    k_fill<<<nseg, 32>>>(n_win, out);
}

// round 5
// speedup vs baseline: 1.2079x; 1.0471x over previous
#include <cuda_runtime.h>
#include <stdint.h>

#define WIN   442
#define NBINS 221
#define HOP   4
#define RELC  0.0594f
#define CWIN  256           // windows per DFT block
#define SEG   2048          // windows per scan segment
#define MAXWIN 262144
#define MAXSEG (MAXWIN / SEG)

typedef unsigned long long u64;

__device__ float g_ct_hi[WIN];
__device__ float g_ct_lo[WIN];
__device__ float g_st_hi[WIN];
__device__ float g_st_lo[WIN];
__device__ u64   g_cst[WIN];                 // packed (cos_hi, sin_hi)
__device__ int   g_bins[MAXWIN];
__device__ __align__(16) unsigned g_mapsP[MAXSEG * NBINS];
__device__ int2  g_segin[MAXSEG];

// ---------------------------------------------------------------------------
// Twiddle tables: cos/sin(2*pi*m/442) as double-float (hi, lo) pairs, plus a
// packed (cos_hi, sin_hi) table for f32x2 consumption.
// ---------------------------------------------------------------------------
__global__ void k_init_tables() {
    int m = threadIdx.x;
    if (m < WIN) {
        double ang = (2.0 * 3.141592653589793238462643 * (double)m) / (double)WIN;
        double c = cos(ang), s = sin(ang);
        float ch = (float)c, sh = (float)s;
        g_ct_hi[m] = ch; g_ct_lo[m] = (float)(c - (double)ch);
        g_st_hi[m] = sh; g_st_lo[m] = (float)(s - (double)sh);
        g_cst[m] = ((u64)__float_as_uint(sh) << 32) | (u64)__float_as_uint(ch);
    }
}

// ---------------------------------------------------------------------------
// Packed f32x2 primitives (component 0 = low = re/cos path, component 1 = im/sin).
// Componentwise RN rounding == scalar ops, so numerics are bit-identical.
// Negation = sign-bit XOR (alu pipe, exact).
// ---------------------------------------------------------------------------
__device__ __forceinline__ u64 pk2(float lo, float hi) {
    u64 r; asm("mov.b64 %0, {%1, %2};" : "=l"(r) : "f"(lo), "f"(hi)); return r;
}
__device__ __forceinline__ void upk2(u64 v, float& lo, float& hi) {
    asm("mov.b64 {%0, %1}, %2;" : "=f"(lo), "=f"(hi) : "l"(v));
}
__device__ __forceinline__ u64 fma2(u64 a, u64 b, u64 c) {
    u64 r; asm("fma.rn.f32x2 %0, %1, %2, %3;" : "=l"(r) : "l"(a), "l"(b), "l"(c)); return r;
}
__device__ __forceinline__ u64 add2(u64 a, u64 b) {
    u64 r; asm("add.rn.f32x2 %0, %1, %2;" : "=l"(r) : "l"(a), "l"(b)); return r;
}
__device__ __forceinline__ u64 mul2(u64 a, u64 b) {
    u64 r; asm("mul.rn.f32x2 %0, %1, %2;" : "=l"(r) : "l"(a), "l"(b)); return r;
}
__device__ __forceinline__ u64 neg2(u64 a) { return a ^ 0x8000000080000000ull; }

// exact two_sum, both components at once (== scalar Knuth two_sum per lane)
__device__ __forceinline__ void two_sum2(u64 a, u64 b, u64& s, u64& e) {
    s = add2(a, b);
    u64 bp = add2(s, neg2(a));
    u64 t  = add2(s, neg2(bp));
    u64 d1 = add2(a, neg2(t));
    u64 d2 = add2(b, neg2(bp));
    e = add2(d1, d2);
}

// ---------------------------------------------------------------------------
// DFT + argmax. One block = 256 consecutive windows, thread k = bin k.
// State (re,im) carried as packed double-float: RH=(re_hi,im_hi), RL=(re_lo,im_lo).
// Direct 442-tap DFT with compensated accumulation; 255 hop-4 slides with
// double-float rotation. All heavy math in f32x2 (2 lanes per fma-pipe slot).
// ---------------------------------------------------------------------------
__global__ __launch_bounds__(224) void k_dft(const float* __restrict__ x, int n_win) {
    __shared__ float xs[WIN + 4 * CWIN];     // 1466 samples
    __shared__ u64   cst[WIN];               // packed (cos, sin)
    __shared__ unsigned long long wk[CWIN][7];

    const int tid = threadIdx.x;
    const int w0  = blockIdx.x * CWIN;
    const int nc  = min(CWIN, n_win - w0);
    const int s0  = w0 * HOP;
    const int L   = 4 * nc + 438;

    for (int i = tid; i < L; i += blockDim.x)   xs[i]  = x[s0 + i];
    for (int i = tid; i < WIN; i += blockDim.x) cst[i] = g_cst[i];
    __syncthreads();

    const int k    = tid;
    const int lane = tid & 31;
    const int wid  = tid >> 5;
    const bool act = (k < NBINS);

    // packed per-bin constants
    u64 C1 = 0, C2 = 0, C3 = 0;                 // (c_j, -s_j) for delta path
    u64 Wc = 0, WcL = 0, Ws = 0, WsL = 0;       // rotation twiddle, signs baked
    if (act) {
        float c1, s1, c2, s2, c3, s3;
        upk2(cst[k], c1, s1);
        upk2(cst[2 * k], c2, s2);
        int i3 = 3 * k;  if (i3 >= WIN) i3 -= WIN;
        upk2(cst[i3], c3, s3);
        C1 = pk2(c1, -s1); C2 = pk2(c2, -s2); C3 = pk2(c3, -s3);
        int i4 = 4 * k;  if (i4 >= WIN) i4 -= WIN;
        float wch = g_ct_hi[i4], wcl = g_ct_lo[i4];
        float wsh = g_st_hi[i4], wsl = g_st_lo[i4];
        Wc  = pk2(wch,  wsh);   WcL = pk2(wcl,  wsl);
        Ws  = pk2(-wsh, wch);   WsL = pk2(-wsl, wcl);
    }

    // direct DFT of first window, compensated: X[k] = sum x_n (cos - i sin)
    u64 RH = 0ull, RL = 0ull;   // (re_hi, im_hi), (re_lo, im_lo)
    if (act) {
        int idx = 0;
        #pragma unroll 2
        for (int nn = 0; nn < WIN; nn++) {
            float xv = xs[nn];
            u64 XV = pk2(xv, xv);
            u64 P  = mul2(XV, cst[idx]);
            u64 s, e;
            two_sum2(RH, P, s, e);
            RH = s;
            RL = add2(RL, e);
            idx += k; if (idx >= WIN) idx -= WIN;
        }
        // im = -im  (flip sign of high component only; exact)
        RH ^= 0x8000000000000000ull;
        RL ^= 0x8000000000000000ull;
    }

    for (int w = 0; w < nc; w++) {
        float rh, ih, rl, il;
        upk2(RH, rh, ih); upk2(RL, rl, il);
        float rv  = __fadd_rn(rh, rl);
        float iv  = __fadd_rn(ih, il);
        float mag = act ? __fadd_rn(fabsf(rv), fabsf(iv)) : -1.0f;

        // warp argmax: fp32 max-reduce + equality ballot (ties -> lowest bin)
        float mx = mag;
        #pragma unroll
        for (int o = 16; o > 0; o >>= 1)
            mx = fmaxf(mx, __shfl_xor_sync(0xffffffffu, mx, o));
        unsigned eq = __ballot_sync(0xffffffffu, mag == mx);
        if (lane == 0) {
            unsigned bin = (unsigned)(wid * 32 + (__ffs(eq) - 1));
            wk[w][wid] = (((unsigned long long)__float_as_uint(mx)) << 32)
                         | (unsigned long long)(0xFFFFFFFFu - bin);
        }

        if (w + 1 < nc && act) {
            int p = 4 * w;
            float d0 = __fsub_rn(xs[p + 442], xs[p]);
            float d1 = __fsub_rn(xs[p + 443], xs[p + 1]);
            float d2 = __fsub_rn(xs[p + 444], xs[p + 2]);
            float d3 = __fsub_rn(xs[p + 445], xs[p + 3]);

            // D = (dre, dim): dre = d0 + d1 c1 + d2 c2 + d3 c3
            //                 dim = -d1 s1 - d2 s2 - d3 s3
            u64 D = fma2(pk2(d1, d1), C1, pk2(d0, 0.0f));
            D = fma2(pk2(d2, d2), C2, D);
            D = fma2(pk2(d3, d3), C3, D);

            // fold deltas into lo word
            u64 RLf = add2(RL, D);

            // rotation: re' = ar*wc - ai*ws ; im' = ar*ws + ai*wc (double-float)
            float ar, ai, arl, ail;
            upk2(RH, ar, ai); upk2(RLf, arl, ail);
            u64 A  = pk2(ar,  ar),  Ai  = pk2(ai,  ai);
            u64 Al = pk2(arl, arl), Ail = pk2(ail, ail);

            u64 P2 = mul2(A, Wc);                 // (p, r)
            u64 Pl = fma2(A, Wc, neg2(P2));       // exact product error
            Pl = fma2(A,  WcL, Pl);
            Pl = fma2(Al, Wc,  Pl);

            u64 Q2 = mul2(Ai, Ws);                // (-q, u)
            u64 Ql = fma2(Ai, Ws, neg2(Q2));
            Ql = fma2(Ai,  WsL, Ql);
            Ql = fma2(Ail, Ws,  Ql);

            u64 S, E;
            two_sum2(P2, Q2, S, E);
            u64 nlo = add2(E, add2(Pl, Ql));
            RH = add2(S, nlo);
            RL = add2(add2(S, neg2(RH)), nlo);
        }
    }
    __syncthreads();

    for (int i = tid; i < nc; i += blockDim.x) {
        unsigned long long m = wk[i][0];
        #pragma unroll
        for (int j = 1; j < 7; j++) if (wk[i][j] > m) m = wk[i][j];
        g_bins[w0 + i] = (int)(0xFFFFFFFFu - (unsigned)(m & 0xFFFFFFFFull));
    }
}

// ---------------------------------------------------------------------------
// Scan phase 1: per-segment transition maps, written PACKED:
// (global_reset_time << 8) | bin, sentinel 0xFFFFFFFF = state survives.
// ---------------------------------------------------------------------------
__global__ void k_segmaps(int n_win) {
    __shared__ int   sb[SEG];
    __shared__ short sj[SEG];
    const int seg = blockIdx.x;
    const int s0  = seg * SEG;
    const int len = min(SEG, n_win - s0);

    for (int i = threadIdx.x; i < SEG; i += blockDim.x)
        sb[i] = (i < len) ? g_bins[s0 + i] : 0;
    __syncthreads();

    for (int p = threadIdx.x; p < len; p += blockDim.x) {
        float F   = 100.0f * (float)sb[p];
        float thr = F * RELC;
        int j = p + 1;
        while (j < len && fabsf(F - 100.0f * (float)sb[j]) <= thr) j++;
        sj[p] = (short)((j < len) ? j : p);      // self-loop == terminal
    }
    __syncthreads();

    for (int r = 0; r < 11; r++) {               // log2(2048) rounds
        for (int p = threadIdx.x; p < len; p += blockDim.x)
            sj[p] = sj[sj[p]];
        __syncthreads();
    }

    for (int f = threadIdx.x; f < NBINS; f += blockDim.x) {
        float F   = 100.0f * (float)f;
        float thr = F * RELC;
        int j = 0;
        while (j < len && fabsf(F - 100.0f * (float)sb[j]) <= thr) j++;
        unsigned v;
        if (j >= len) v = 0xFFFFFFFFu;
        else { int term = sj[j]; v = (((unsigned)(s0 + term)) << 8) | (unsigned)sb[term]; }
        g_mapsP[seg * NBINS + f] = v;
    }
}

// ---------------------------------------------------------------------------
// Scan phase 2: bulk-load packed maps (108 KB) with wide uint4 loads and
// 1024 threads (deep MLP), then thread 0 walks the chain in shared memory.
// ---------------------------------------------------------------------------
__global__ void k_walk(int n_win, int nseg, float* __restrict__ out) {
    extern __shared__ unsigned sm[];
    const int tot  = nseg * NBINS;
    const int tot4 = tot >> 2;
    const uint4* src4 = (const uint4*)g_mapsP;
    uint4* dst4 = (uint4*)sm;
    for (int i = threadIdx.x; i < tot4; i += blockDim.x) dst4[i] = src4[i];
    for (int i = (tot4 << 2) + threadIdx.x; i < tot; i += blockDim.x) sm[i] = g_mapsP[i];
    __syncthreads();

    if (threadIdx.x == 0) {
        int bF = 0, Tw = 0;
        for (int s = 0; s < nseg; s++) {
            g_segin[s] = make_int2(bF, Tw);
            unsigned v = sm[s * NBINS + bF];
            if (v != 0xFFFFFFFFu) { bF = (int)(v & 0xFFu); Tw = (int)(v >> 8); }
        }
        float F    = 100.0f * (float)bF;
        float Ft   = 4.0f * (float)Tw;
        float last = 4.0f * (float)(n_win - 1);
        out[3 * n_win + 0] = F;
        out[3 * n_win + 1] = __fdiv_rn((last - Ft) * 1000.0f, 44100.0f);
    }
}

// ---------------------------------------------------------------------------
// Scan phase 3: parallel fill. One warp per segment replays the exact
// reference emit semantics (cond/emit use PRE-update state) via ballots.
// ---------------------------------------------------------------------------
__global__ void k_fill(int n_win, float* __restrict__ out) {
    const int seg = blockIdx.x;
    const int s0  = seg * SEG;
    const int len = min(SEG, n_win - s0);
    const int lane = threadIdx.x;

    int2 st0 = g_segin[seg];
    float F = 100.0f * (float)st0.x;
    float T = 4.0f * (float)st0.y;

    float* flags = out;
    float* freqs = out + n_win;
    float* durs  = out + 2 * n_win;

    for (int base = 0; base < len; base += 32) {
        int  i     = s0 + base + lane;
        bool valid = (base + lane) < len;
        float t = valid ? 100.0f * (float)g_bins[i] : 0.0f;

        unsigned rem = __ballot_sync(0xffffffffu, valid);
        float myF = 0.f, myT = 0.f;
        bool  myc = false;
        while (rem) {
            bool oob = fabsf(F - t) > F * RELC;
            unsigned bal = __ballot_sync(0xffffffffu, oob) & rem;
            if (!bal) {
                if (rem & (1u << lane)) { myF = F; myT = T; }
                break;
            }
            int e = __ffs(bal) - 1;
            if ((rem & (1u << lane)) && lane <= e) {
                myF = F; myT = T; myc = (lane == e);
            }
            F = __shfl_sync(0xffffffffu, t, e);
            T = 4.0f * (float)(s0 + base + e);
            unsigned below = (e == 31) ? 0xffffffffu : ((1u << (e + 1)) - 1u);
            rem &= ~below;
        }
        if (valid) {
            flags[i] = myc ? 1.0f : 0.0f;
            freqs[i] = myF;
            durs[i]  = __fdiv_rn(((float)(4 * i) - myT) * 1000.0f, 44100.0f);
        }
    }
}

// ---------------------------------------------------------------------------
extern "C" void kernel_launch(void* const* d_in, const int* in_sizes, int n_in,
                              void* d_out, int out_size) {
    const float* x = (const float*)d_in[0];
    int n     = in_sizes[0];
    int n_win = (n - WIN + HOP - 1) / HOP;
    if (n_win > MAXWIN) n_win = MAXWIN;   // safety cap (fixed input: 249890)
    int nblk = (n_win + CWIN - 1) / CWIN;
    int nseg = (n_win + SEG - 1) / SEG;
    float* out = (float*)d_out;

    size_t walk_smem = (size_t)nseg * NBINS * sizeof(unsigned);  // ~108.7 KB
    static bool attr_done = false;
    if (!attr_done) {
        cudaFuncSetAttribute(k_walk, cudaFuncAttributeMaxDynamicSharedMemorySize,
                             (int)(116 * 1024));
        attr_done = true;
    }

    k_init_tables<<<1, 448>>>();
    k_dft<<<nblk, 224>>>(x, n_win);
    k_segmaps<<<nseg, 256>>>(n_win);
    k_walk<<<1, 1024, walk_smem>>>(n_win, nseg, out);
    k_fill<<<nseg, 32>>>(n_win, out);
}

// round 6
// speedup vs baseline: 1.2796x; 1.0594x over previous
#include <cuda_runtime.h>
#include <stdint.h>

#define WIN   442
#define NBINS 221
#define HOP   4
#define RELC  0.0594f
#define CWIN  256           // windows per DFT block
#define SEG   2048          // windows per scan segment
#define MAXWIN 262144
#define MAXSEG (MAXWIN / SEG)

typedef unsigned long long u64;

__device__ float g_ct_hi[WIN];
__device__ float g_ct_lo[WIN];
__device__ float g_st_hi[WIN];
__device__ float g_st_lo[WIN];
__device__ u64   g_cst[WIN];                 // packed (cos_hi, sin_hi)
__device__ int   g_bins[MAXWIN];
__device__ __align__(16) unsigned g_mapsP[MAXSEG * NBINS];
__device__ int2  g_segin[MAXSEG];

// ---------------------------------------------------------------------------
// Twiddle tables: cos/sin(2*pi*m/442) as double-float (hi, lo) pairs, plus a
// packed (cos_hi, sin_hi) table for f32x2 consumption.
// ---------------------------------------------------------------------------
__global__ void k_init_tables() {
    int m = threadIdx.x;
    if (m < WIN) {
        double ang = (2.0 * 3.141592653589793238462643 * (double)m) / (double)WIN;
        double c = cos(ang), s = sin(ang);
        float ch = (float)c, sh = (float)s;
        g_ct_hi[m] = ch; g_ct_lo[m] = (float)(c - (double)ch);
        g_st_hi[m] = sh; g_st_lo[m] = (float)(s - (double)sh);
        g_cst[m] = ((u64)__float_as_uint(sh) << 32) | (u64)__float_as_uint(ch);
    }
}

// ---------------------------------------------------------------------------
// Packed f32x2 primitives (component 0 = low = re/cos path, component 1 = im/sin).
// Componentwise RN rounding == scalar ops, so numerics are bit-identical.
// ---------------------------------------------------------------------------
__device__ __forceinline__ u64 pk2(float lo, float hi) {
    u64 r; asm("mov.b64 %0, {%1, %2};" : "=l"(r) : "f"(lo), "f"(hi)); return r;
}
__device__ __forceinline__ void upk2(u64 v, float& lo, float& hi) {
    asm("mov.b64 {%0, %1}, %2;" : "=f"(lo), "=f"(hi) : "l"(v));
}
__device__ __forceinline__ u64 fma2(u64 a, u64 b, u64 c) {
    u64 r; asm("fma.rn.f32x2 %0, %1, %2, %3;" : "=l"(r) : "l"(a), "l"(b), "l"(c)); return r;
}
__device__ __forceinline__ u64 add2(u64 a, u64 b) {
    u64 r; asm("add.rn.f32x2 %0, %1, %2;" : "=l"(r) : "l"(a), "l"(b)); return r;
}
__device__ __forceinline__ u64 mul2(u64 a, u64 b) {
    u64 r; asm("mul.rn.f32x2 %0, %1, %2;" : "=l"(r) : "l"(a), "l"(b)); return r;
}
__device__ __forceinline__ u64 neg2(u64 a) { return a ^ 0x8000000080000000ull; }

// exact two_sum, both components at once (== scalar Knuth two_sum per lane)
__device__ __forceinline__ void two_sum2(u64 a, u64 b, u64& s, u64& e) {
    s = add2(a, b);
    u64 bp = add2(s, neg2(a));
    u64 t  = add2(s, neg2(bp));
    u64 d1 = add2(a, neg2(t));
    u64 d2 = add2(b, neg2(bp));
    e = add2(d1, d2);
}

__device__ __forceinline__ unsigned redux_max_u32(unsigned v) {
    unsigned r;
    asm("redux.sync.max.u32 %0, %1, 0xffffffff;" : "=r"(r) : "r"(v));
    return r;
}

// ---------------------------------------------------------------------------
// DFT + argmax. One block = 256 consecutive windows, thread k = bin k.
// State (re,im) carried as packed double-float: RH=(re_hi,im_hi), RL=(re_lo,im_lo).
// Direct 442-tap DFT with compensated accumulation; 255 hop-4 slides with
// double-float rotation. __launch_bounds__(224,2) pins >=2 blocks/SM so the
// dependent rotation chains are latency-hidden by ~3.5 warps/SMSP.
// Per-window argmax: one redux.sync.max.u32 + equality ballot (ties -> lowest
// bin, matching jnp.argmax); cross-warp 64-bit key merge at the end.
// ---------------------------------------------------------------------------
__global__ __launch_bounds__(224, 2) void k_dft(const float* __restrict__ x, int n_win) {
    __shared__ float xs[WIN + 4 * CWIN];     // 1466 samples
    __shared__ u64   cst[WIN];               // packed (cos, sin)
    __shared__ unsigned long long wk[CWIN][7];

    const int tid = threadIdx.x;
    const int w0  = blockIdx.x * CWIN;
    const int nc  = min(CWIN, n_win - w0);
    const int s0  = w0 * HOP;
    const int L   = 4 * nc + 438;

    for (int i = tid; i < L; i += blockDim.x)   xs[i]  = x[s0 + i];
    for (int i = tid; i < WIN; i += blockDim.x) cst[i] = g_cst[i];
    __syncthreads();

    const int k    = tid;
    const int lane = tid & 31;
    const int wid  = tid >> 5;
    const bool act = (k < NBINS);

    // packed per-bin constants
    u64 C1 = 0, C2 = 0, C3 = 0;                 // (c_j, -s_j) for delta path
    u64 Wc = 0, WcL = 0, Ws = 0, WsL = 0;       // rotation twiddle, signs baked
    if (act) {
        float c1, s1, c2, s2, c3, s3;
        upk2(cst[k], c1, s1);
        upk2(cst[2 * k], c2, s2);
        int i3 = 3 * k;  if (i3 >= WIN) i3 -= WIN;
        upk2(cst[i3], c3, s3);
        C1 = pk2(c1, -s1); C2 = pk2(c2, -s2); C3 = pk2(c3, -s3);
        int i4 = 4 * k;  if (i4 >= WIN) i4 -= WIN;
        float wch = g_ct_hi[i4], wcl = g_ct_lo[i4];
        float wsh = g_st_hi[i4], wsl = g_st_lo[i4];
        Wc  = pk2(wch,  wsh);   WcL = pk2(wcl,  wsl);
        Ws  = pk2(-wsh, wch);   WsL = pk2(-wsl, wcl);
    }

    // direct DFT of first window, compensated: X[k] = sum x_n (cos - i sin)
    u64 RH = 0ull, RL = 0ull;   // (re_hi, im_hi), (re_lo, im_lo)
    if (act) {
        int idx = 0;
        #pragma unroll 2
        for (int nn = 0; nn < WIN; nn++) {
            float xv = xs[nn];
            u64 XV = pk2(xv, xv);
            u64 P  = mul2(XV, cst[idx]);
            u64 s, e;
            two_sum2(RH, P, s, e);
            RH = s;
            RL = add2(RL, e);
            idx += k; if (idx >= WIN) idx -= WIN;
        }
        // im = -im  (flip sign of high component only; exact)
        RH ^= 0x8000000000000000ull;
        RL ^= 0x8000000000000000ull;
    }

    for (int w = 0; w < nc; w++) {
        float rh, ih, rl, il;
        upk2(RH, rh, ih); upk2(RL, rl, il);
        float rv  = __fadd_rn(rh, rl);
        float iv  = __fadd_rn(ih, il);
        float mag = __fadd_rn(fabsf(rv), fabsf(iv));
        // nonneg float bits are order-isomorphic to uint
        unsigned mbits = act ? __float_as_uint(mag) : 0u;

        unsigned mx = redux_max_u32(mbits);
        unsigned eq = __ballot_sync(0xffffffffu, mbits == mx);
        if (lane == 0) {
            unsigned bin = (unsigned)(wid * 32 + (__ffs(eq) - 1));
            wk[w][wid] = (((unsigned long long)mx) << 32)
                         | (unsigned long long)(0xFFFFFFFFu - bin);
        }

        if (w + 1 < nc && act) {
            int p = 4 * w;
            float d0 = __fsub_rn(xs[p + 442], xs[p]);
            float d1 = __fsub_rn(xs[p + 443], xs[p + 1]);
            float d2 = __fsub_rn(xs[p + 444], xs[p + 2]);
            float d3 = __fsub_rn(xs[p + 445], xs[p + 3]);

            // D = (dre, dim): dre = d0 + d1 c1 + d2 c2 + d3 c3
            //                 dim = -d1 s1 - d2 s2 - d3 s3
            u64 D = fma2(pk2(d1, d1), C1, pk2(d0, 0.0f));
            D = fma2(pk2(d2, d2), C2, D);
            D = fma2(pk2(d3, d3), C3, D);

            // fold deltas into lo word
            u64 RLf = add2(RL, D);

            // rotation: re' = ar*wc - ai*ws ; im' = ar*ws + ai*wc (double-float)
            float ar, ai, arl, ail;
            upk2(RH, ar, ai); upk2(RLf, arl, ail);
            u64 A  = pk2(ar,  ar),  Ai  = pk2(ai,  ai);
            u64 Al = pk2(arl, arl), Ail = pk2(ail, ail);

            u64 P2 = mul2(A, Wc);                 // (p, r)
            u64 Pl = fma2(A, Wc, neg2(P2));       // exact product error
            Pl = fma2(A,  WcL, Pl);
            Pl = fma2(Al, Wc,  Pl);

            u64 Q2 = mul2(Ai, Ws);                // (-q, u)
            u64 Ql = fma2(Ai, Ws, neg2(Q2));
            Ql = fma2(Ai,  WsL, Ql);
            Ql = fma2(Ail, Ws,  Ql);

            u64 S, E;
            two_sum2(P2, Q2, S, E);
            u64 nlo = add2(E, add2(Pl, Ql));
            RH = add2(S, nlo);
            RL = add2(add2(S, neg2(RH)), nlo);
        }
    }
    __syncthreads();

    for (int i = tid; i < nc; i += blockDim.x) {
        unsigned long long m = wk[i][0];
        #pragma unroll
        for (int j = 1; j < 7; j++) if (wk[i][j] > m) m = wk[i][j];
        g_bins[w0 + i] = (int)(0xFFFFFFFFu - (unsigned)(m & 0xFFFFFFFFull));
    }
}

// ---------------------------------------------------------------------------
// Scan phase 1: per-segment transition maps, written PACKED:
// (global_reset_time << 8) | bin, sentinel 0xFFFFFFFF = state survives.
// ---------------------------------------------------------------------------
__global__ void k_segmaps(int n_win) {
    __shared__ int   sb[SEG];
    __shared__ short sj[SEG];
    const int seg = blockIdx.x;
    const int s0  = seg * SEG;
    const int len = min(SEG, n_win - s0);

    for (int i = threadIdx.x; i < SEG; i += blockDim.x)
        sb[i] = (i < len) ? g_bins[s0 + i] : 0;
    __syncthreads();

    for (int p = threadIdx.x; p < len; p += blockDim.x) {
        float F   = 100.0f * (float)sb[p];
        float thr = F * RELC;
        int j = p + 1;
        while (j < len && fabsf(F - 100.0f * (float)sb[j]) <= thr) j++;
        sj[p] = (short)((j < len) ? j : p);      // self-loop == terminal
    }
    __syncthreads();

    for (int r = 0; r < 11; r++) {               // log2(2048) rounds
        for (int p = threadIdx.x; p < len; p += blockDim.x)
            sj[p] = sj[sj[p]];
        __syncthreads();
    }

    for (int f = threadIdx.x; f < NBINS; f += blockDim.x) {
        float F   = 100.0f * (float)f;
        float thr = F * RELC;
        int j = 0;
        while (j < len && fabsf(F - 100.0f * (float)sb[j]) <= thr) j++;
        unsigned v;
        if (j >= len) v = 0xFFFFFFFFu;
        else { int term = sj[j]; v = (((unsigned)(s0 + term)) << 8) | (unsigned)sb[term]; }
        g_mapsP[seg * NBINS + f] = v;
    }
}

// ---------------------------------------------------------------------------
// Scan phase 2: bulk-load packed maps (108 KB) with wide uint4 loads and
// 1024 threads (deep MLP), then thread 0 walks the chain in shared memory.
// ---------------------------------------------------------------------------
__global__ void k_walk(int n_win, int nseg, float* __restrict__ out) {
    extern __shared__ unsigned sm[];
    const int tot  = nseg * NBINS;
    const int tot4 = tot >> 2;
    const uint4* src4 = (const uint4*)g_mapsP;
    uint4* dst4 = (uint4*)sm;
    for (int i = threadIdx.x; i < tot4; i += blockDim.x) dst4[i] = src4[i];
    for (int i = (tot4 << 2) + threadIdx.x; i < tot; i += blockDim.x) sm[i] = g_mapsP[i];
    __syncthreads();

    if (threadIdx.x == 0) {
        int bF = 0, Tw = 0;
        for (int s = 0; s < nseg; s++) {
            g_segin[s] = make_int2(bF, Tw);
            unsigned v = sm[s * NBINS + bF];
            if (v != 0xFFFFFFFFu) { bF = (int)(v & 0xFFu); Tw = (int)(v >> 8); }
        }
        float F    = 100.0f * (float)bF;
        float Ft   = 4.0f * (float)Tw;
        float last = 4.0f * (float)(n_win - 1);
        out[3 * n_win + 0] = F;
        out[3 * n_win + 1] = __fdiv_rn((last - Ft) * 1000.0f, 44100.0f);
    }
}

// ---------------------------------------------------------------------------
// Scan phase 3: parallel fill. One warp per segment replays the exact
// reference emit semantics (cond/emit use PRE-update state) via ballots.
// ---------------------------------------------------------------------------
__global__ void k_fill(int n_win, float* __restrict__ out) {
    const int seg = blockIdx.x;
    const int s0  = seg * SEG;
    const int len = min(SEG, n_win - s0);
    const int lane = threadIdx.x;

    int2 st0 = g_segin[seg];
    float F = 100.0f * (float)st0.x;
    float T = 4.0f * (float)st0.y;

    float* flags = out;
    float* freqs = out + n_win;
    float* durs  = out + 2 * n_win;

    for (int base = 0; base < len; base += 32) {
        int  i     = s0 + base + lane;
        bool valid = (base + lane) < len;
        float t = valid ? 100.0f * (float)g_bins[i] : 0.0f;

        unsigned rem = __ballot_sync(0xffffffffu, valid);
        float myF = 0.f, myT = 0.f;
        bool  myc = false;
        while (rem) {
            bool oob = fabsf(F - t) > F * RELC;
            unsigned bal = __ballot_sync(0xffffffffu, oob) & rem;
            if (!bal) {
                if (rem & (1u << lane)) { myF = F; myT = T; }
                break;
            }
            int e = __ffs(bal) - 1;
            if ((rem & (1u << lane)) && lane <= e) {
                myF = F; myT = T; myc = (lane == e);
            }
            F = __shfl_sync(0xffffffffu, t, e);
            T = 4.0f * (float)(s0 + base + e);
            unsigned below = (e == 31) ? 0xffffffffu : ((1u << (e + 1)) - 1u);
            rem &= ~below;
        }
        if (valid) {
            flags[i] = myc ? 1.0f : 0.0f;
            freqs[i] = myF;
            durs[i]  = __fdiv_rn(((float)(4 * i) - myT) * 1000.0f, 44100.0f);
        }
    }
}

// ---------------------------------------------------------------------------
extern "C" void kernel_launch(void* const* d_in, const int* in_sizes, int n_in,
                              void* d_out, int out_size) {
    const float* x = (const float*)d_in[0];
    int n     = in_sizes[0];
    int n_win = (n - WIN + HOP - 1) / HOP;
    if (n_win > MAXWIN) n_win = MAXWIN;   // safety cap (fixed input: 249890)
    int nblk = (n_win + CWIN - 1) / CWIN;
    int nseg = (n_win + SEG - 1) / SEG;
    float* out = (float*)d_out;

    size_t walk_smem = (size_t)nseg * NBINS * sizeof(unsigned);  // ~108.7 KB
    static bool attr_done = false;
    if (!attr_done) {
        cudaFuncSetAttribute(k_walk, cudaFuncAttributeMaxDynamicSharedMemorySize,
                             (int)(116 * 1024));
        attr_done = true;
    }

    k_init_tables<<<1, 448>>>();
    k_dft<<<nblk, 224>>>(x, n_win);
    k_segmaps<<<nseg, 256>>>(n_win);
    k_walk<<<1, 1024, walk_smem>>>(n_win, nseg, out);
    k_fill<<<nseg, 32>>>(n_win, out);
}

// round 7
// speedup vs baseline: 1.3970x; 1.0917x over previous
#include <cuda_runtime.h>
#include <stdint.h>

#define WIN   442
#define NBINS 221
#define HOP   4
#define RELC  0.0594f
#define CWIN  512           // windows per DFT block
#define SEG   2048          // windows per scan segment
#define MAXWIN 262144
#define MAXSEG (MAXWIN / SEG)
#define CSCSZ (WIN + (WIN >> 4) + 1)   // skewed LUT size (442 + 27)

typedef unsigned long long u64;

__device__ u64   g_csc[WIN];                 // packed (cos, -sin)
__device__ int   g_bins[MAXWIN];
__device__ __align__(16) unsigned g_mapsP[MAXSEG * NBINS];
__device__ int2  g_segin[MAXSEG];

// ---------------------------------------------------------------------------
// Twiddle LUT: csc[m] = (cos(2pi m/442), -sin(2pi m/442)) packed, fp32.
// ---------------------------------------------------------------------------
__global__ void k_init_tables() {
    int m = threadIdx.x;
    if (m < WIN) {
        double ang = (2.0 * 3.141592653589793238462643 * (double)m) / (double)WIN;
        float c = (float)cos(ang), s = (float)sin(ang);
        g_csc[m] = ((u64)__float_as_uint(-s) << 32) | (u64)__float_as_uint(c);
    }
}

// ---------------------------------------------------------------------------
// Packed f32x2 primitives (lane0 = re path, lane1 = im path). Componentwise
// RN rounding == scalar ops. Negation = sign XOR (alu pipe, exact).
// ---------------------------------------------------------------------------
__device__ __forceinline__ u64 pk2(float lo, float hi) {
    u64 r; asm("mov.b64 %0, {%1, %2};" : "=l"(r) : "f"(lo), "f"(hi)); return r;
}
__device__ __forceinline__ void upk2(u64 v, float& lo, float& hi) {
    asm("mov.b64 {%0, %1}, %2;" : "=f"(lo), "=f"(hi) : "l"(v));
}
__device__ __forceinline__ u64 fma2(u64 a, u64 b, u64 c) {
    u64 r; asm("fma.rn.f32x2 %0, %1, %2, %3;" : "=l"(r) : "l"(a), "l"(b), "l"(c)); return r;
}
__device__ __forceinline__ u64 add2(u64 a, u64 b) {
    u64 r; asm("add.rn.f32x2 %0, %1, %2;" : "=l"(r) : "l"(a), "l"(b)); return r;
}
__device__ __forceinline__ u64 mul2(u64 a, u64 b) {
    u64 r; asm("mul.rn.f32x2 %0, %1, %2;" : "=l"(r) : "l"(a), "l"(b)); return r;
}
__device__ __forceinline__ u64 neg2(u64 a) { return a ^ 0x8000000080000000ull; }

// Kahan compensated accumulation, both components at once.
__device__ __forceinline__ void kadd(u64& S, u64& C, u64 P) {
    u64 y = add2(P, neg2(C));
    u64 t = add2(S, y);
    C = add2(add2(t, neg2(S)), neg2(y));
    S = t;
}

__device__ __forceinline__ unsigned redux_max_u32(unsigned v) {
    unsigned r;
    asm("redux.sync.max.u32 %0, %1, 0xffffffff;" : "=r"(r) : "r"(v));
    return r;
}

// skewed LUT index: breaks 16-stride bank conflicts on the 8-byte table
__device__ __forceinline__ int sk(int m) { return m + (m >> 4); }

// ---------------------------------------------------------------------------
// DFT + argmax, rotation-free formulation. One block = 512 windows, thread k
// = bin k. State Y_w = W4^{-w} X_w accumulates ADDITIVELY:
//   Y_{w+1} = Y_w + sum_j d_j * e^{-i th k (4w+j)},  d_j = x[4w+j+442]-x[4w+j]
// (Kahan-compensated f32x2). Magnitude uses X_w = W4^{+w} Y_w via ONE fp32
// rotation from the same LUT (error non-accumulating). Direct DFT of window 0
// uses the identical 4-tap group structure (110 groups + taps 440,441).
// Per-window argmax: redux.sync.max.u32 + equality ballot (ties -> lowest
// bin, matching jnp.argmax); cross-warp 64-bit key merge at the end.
// ---------------------------------------------------------------------------
__global__ __launch_bounds__(224, 2) void k_dft(const float* __restrict__ x, int n_win) {
    __shared__ __align__(16) float xs[WIN + 4 * CWIN];   // 2490 floats
    __shared__ u64 csc[CSCSZ];
    __shared__ u64 wk[CWIN][7];

    const int tid = threadIdx.x;
    const int w0  = blockIdx.x * CWIN;
    const int nc  = min(CWIN, n_win - w0);
    const int s0  = w0 * HOP;
    const int L   = 4 * nc + 438;

    for (int i = tid; i < L; i += blockDim.x) xs[i] = x[s0 + i];
    for (int i = tid; i < WIN; i += blockDim.x) csc[sk(i)] = g_csc[i];
    __syncthreads();

    const int k    = tid;
    const int lane = tid & 31;
    const int wid  = tid >> 5;
    const bool act = (k < NBINS);

    const int step = (4 * k) % WIN;
    const int j1   = k % WIN;                   // k < 442 always
    const int j2   = (2 * k) % WIN;
    const int j3   = (3 * k) % WIN;

    int idx0 = 0, idx1 = j1, idx2 = j2, idx3 = j3;
    u64 YH = 0ull, CC = 0ull;                   // Kahan (sum, compensation)

    // ---- direct DFT of window 0: Y_0 = sum_n x_n (cos - i sin)(nk) ----
    #pragma unroll 2
    for (int g = 0; g < 110; g++) {
        const float4 xv = *(const float4*)&xs[4 * g];
        u64 T0 = csc[sk(idx0)], T1 = csc[sk(idx1)];
        u64 T2 = csc[sk(idx2)], T3 = csc[sk(idx3)];
        u64 P = add2(fma2(pk2(xv.y, xv.y), T1, mul2(pk2(xv.x, xv.x), T0)),
                     fma2(pk2(xv.w, xv.w), T3, mul2(pk2(xv.z, xv.z), T2)));
        kadd(YH, CC, P);
        idx0 += step; if (idx0 >= WIN) idx0 -= WIN;
        idx1 += step; if (idx1 >= WIN) idx1 -= WIN;
        idx2 += step; if (idx2 >= WIN) idx2 -= WIN;
        idx3 += step; if (idx3 >= WIN) idx3 -= WIN;
    }
    {   // tail taps n = 440, 441 (indices are current idx0, idx1)
        float x0 = xs[440], x1 = xs[441];
        u64 P = fma2(pk2(x1, x1), csc[sk(idx1)], mul2(pk2(x0, x0), csc[sk(idx0)]));
        kadd(YH, CC, P);
    }
    // reset counters for the slide phase (window 0 frame)
    idx0 = 0; idx1 = j1; idx2 = j2; idx3 = j3;

    for (int w = 0; w < nc; w++) {
        // ---- magnitude of X_w = W4^{+w} Y_w; W4^{+w} from csc[idx0]=(c,-s)
        float yrh, yih, cr, ci;
        upk2(YH, yrh, yih); upk2(CC, cr, ci);
        float yr = __fsub_rn(yrh, cr);
        float yi = __fsub_rn(yih, ci);
        float tc, nsn;                          // nsn = -sin
        upk2(csc[sk(idx0)], tc, nsn);
        float xr = __fmaf_rn(yi, nsn, __fmul_rn(yr, tc));   // yr c - yi s
        float tt = __fmul_rn(yr, nsn);
        float xi = __fmaf_rn(yi, tc, -tt);                  // yr s + yi c
        float mag = __fadd_rn(fabsf(xr), fabsf(xi));
        unsigned mbits = act ? __float_as_uint(mag) : 0u;

        unsigned mx = redux_max_u32(mbits);
        unsigned eq = __ballot_sync(0xffffffffu, mbits == mx);
        if (lane == 0) {
            unsigned bin = (unsigned)(wid * 32 + (__ffs(eq) - 1));
            wk[w][wid] = (((u64)mx) << 32) | (u64)(0xFFFFFFFFu - bin);
        }

        // ---- slide: Y += sum_j d_j e^{-i th k (4w+j)}
        if (w + 1 < nc) {
            const int p = 4 * w;
            const float4 a  = *(const float4*)&xs[p];
            const float2 b0 = *(const float2*)&xs[p + 442];
            const float2 b1 = *(const float2*)&xs[p + 444];
            float d0 = __fsub_rn(b0.x, a.x);
            float d1 = __fsub_rn(b0.y, a.y);
            float d2 = __fsub_rn(b1.x, a.z);
            float d3 = __fsub_rn(b1.y, a.w);
            u64 T1 = csc[sk(idx1)], T2 = csc[sk(idx2)], T3 = csc[sk(idx3)];
            u64 T0 = csc[sk(idx0)];
            u64 D = add2(fma2(pk2(d1, d1), T1, mul2(pk2(d0, d0), T0)),
                         fma2(pk2(d3, d3), T3, mul2(pk2(d2, d2), T2)));
            kadd(YH, CC, D);
            idx0 += step; if (idx0 >= WIN) idx0 -= WIN;
            idx1 += step; if (idx1 >= WIN) idx1 -= WIN;
            idx2 += step; if (idx2 >= WIN) idx2 -= WIN;
            idx3 += step; if (idx3 >= WIN) idx3 -= WIN;
        }
    }
    __syncthreads();

    for (int i = tid; i < nc; i += blockDim.x) {
        u64 m = wk[i][0];
        #pragma unroll
        for (int j = 1; j < 7; j++) if (wk[i][j] > m) m = wk[i][j];
        g_bins[w0 + i] = (int)(0xFFFFFFFFu - (unsigned)(m & 0xFFFFFFFFull));
    }
}

// ---------------------------------------------------------------------------
// Scan phase 1: per-segment transition maps, written PACKED:
// (global_reset_time << 8) | bin, sentinel 0xFFFFFFFF = state survives.
// ---------------------------------------------------------------------------
__global__ void k_segmaps(int n_win) {
    __shared__ int   sb[SEG];
    __shared__ short sj[SEG];
    const int seg = blockIdx.x;
    const int s0  = seg * SEG;
    const int len = min(SEG, n_win - s0);

    for (int i = threadIdx.x; i < SEG; i += blockDim.x)
        sb[i] = (i < len) ? g_bins[s0 + i] : 0;
    __syncthreads();

    for (int p = threadIdx.x; p < len; p += blockDim.x) {
        float F   = 100.0f * (float)sb[p];
        float thr = F * RELC;
        int j = p + 1;
        while (j < len && fabsf(F - 100.0f * (float)sb[j]) <= thr) j++;
        sj[p] = (short)((j < len) ? j : p);      // self-loop == terminal
    }
    __syncthreads();

    for (int r = 0; r < 11; r++) {               // log2(2048) rounds
        for (int p = threadIdx.x; p < len; p += blockDim.x)
            sj[p] = sj[sj[p]];
        __syncthreads();
    }

    for (int f = threadIdx.x; f < NBINS; f += blockDim.x) {
        float F   = 100.0f * (float)f;
        float thr = F * RELC;
        int j = 0;
        while (j < len && fabsf(F - 100.0f * (float)sb[j]) <= thr) j++;
        unsigned v;
        if (j >= len) v = 0xFFFFFFFFu;
        else { int term = sj[j]; v = (((unsigned)(s0 + term)) << 8) | (unsigned)sb[term]; }
        g_mapsP[seg * NBINS + f] = v;
    }
}

// ---------------------------------------------------------------------------
// Scan phase 2: bulk-load packed maps (108 KB) with wide uint4 loads and
// 1024 threads (deep MLP), then thread 0 walks the chain in shared memory.
// ---------------------------------------------------------------------------
__global__ void k_walk(int n_win, int nseg, float* __restrict__ out) {
    extern __shared__ unsigned sm[];
    const int tot  = nseg * NBINS;
    const int tot4 = tot >> 2;
    const uint4* src4 = (const uint4*)g_mapsP;
    uint4* dst4 = (uint4*)sm;
    for (int i = threadIdx.x; i < tot4; i += blockDim.x) dst4[i] = src4[i];
    for (int i = (tot4 << 2) + threadIdx.x; i < tot; i += blockDim.x) sm[i] = g_mapsP[i];
    __syncthreads();

    if (threadIdx.x == 0) {
        int bF = 0, Tw = 0;
        for (int s = 0; s < nseg; s++) {
            g_segin[s] = make_int2(bF, Tw);
            unsigned v = sm[s * NBINS + bF];
            if (v != 0xFFFFFFFFu) { bF = (int)(v & 0xFFu); Tw = (int)(v >> 8); }
        }
        float F    = 100.0f * (float)bF;
        float Ft   = 4.0f * (float)Tw;
        float last = 4.0f * (float)(n_win - 1);
        out[3 * n_win + 0] = F;
        out[3 * n_win + 1] = __fdiv_rn((last - Ft) * 1000.0f, 44100.0f);
    }
}

// ---------------------------------------------------------------------------
// Scan phase 3: parallel fill. One warp per segment replays the exact
// reference emit semantics (cond/emit use PRE-update state) via ballots.
// ---------------------------------------------------------------------------
__global__ void k_fill(int n_win, float* __restrict__ out) {
    const int seg = blockIdx.x;
    const int s0  = seg * SEG;
    const int len = min(SEG, n_win - s0);
    const int lane = threadIdx.x;

    int2 st0 = g_segin[seg];
    float F = 100.0f * (float)st0.x;
    float T = 4.0f * (float)st0.y;

    float* flags = out;
    float* freqs = out + n_win;
    float* durs  = out + 2 * n_win;

    for (int base = 0; base < len; base += 32) {
        int  i     = s0 + base + lane;
        bool valid = (base + lane) < len;
        float t = valid ? 100.0f * (float)g_bins[i] : 0.0f;

        unsigned rem = __ballot_sync(0xffffffffu, valid);
        float myF = 0.f, myT = 0.f;
        bool  myc = false;
        while (rem) {
            bool oob = fabsf(F - t) > F * RELC;
            unsigned bal = __ballot_sync(0xffffffffu, oob) & rem;
            if (!bal) {
                if (rem & (1u << lane)) { myF = F; myT = T; }
                break;
            }
            int e = __ffs(bal) - 1;
            if ((rem & (1u << lane)) && lane <= e) {
                myF = F; myT = T; myc = (lane == e);
            }
            F = __shfl_sync(0xffffffffu, t, e);
            T = 4.0f * (float)(s0 + base + e);
            unsigned below = (e == 31) ? 0xffffffffu : ((1u << (e + 1)) - 1u);
            rem &= ~below;
        }
        if (valid) {
            flags[i] = myc ? 1.0f : 0.0f;
            freqs[i] = myF;
            durs[i]  = __fdiv_rn(((float)(4 * i) - myT) * 1000.0f, 44100.0f);
        }
    }
}

// ---------------------------------------------------------------------------
extern "C" void kernel_launch(void* const* d_in, const int* in_sizes, int n_in,
                              void* d_out, int out_size) {
    const float* x = (const float*)d_in[0];
    int n     = in_sizes[0];
    int n_win = (n - WIN + HOP - 1) / HOP;
    if (n_win > MAXWIN) n_win = MAXWIN;   // safety cap (fixed input: 249890)
    int nblk = (n_win + CWIN - 1) / CWIN;
    int nseg = (n_win + SEG - 1) / SEG;
    float* out = (float*)d_out;

    size_t walk_smem = (size_t)nseg * NBINS * sizeof(unsigned);  // ~108.7 KB
    static bool attr_done = false;
    if (!attr_done) {
        cudaFuncSetAttribute(k_walk, cudaFuncAttributeMaxDynamicSharedMemorySize,
                             (int)(116 * 1024));
        attr_done = true;
    }

    k_init_tables<<<1, 448>>>();
    k_dft<<<nblk, 224>>>(x, n_win);
    k_segmaps<<<nseg, 256>>>(n_win);
    k_walk<<<1, 1024, walk_smem>>>(n_win, nseg, out);
    k_fill<<<nseg, 32>>>(n_win, out);
}

// round 8
// speedup vs baseline: 1.5179x; 1.0866x over previous
#include <cuda_runtime.h>
#include <stdint.h>

#define WIN   442
#define NBINS 221
#define HOP   4
#define RELC  0.0594f
#define CWIN  576           // windows per DFT block -> 434 blocks = ONE wave @ occ3
#define SEG   2048          // windows per scan segment
#define MAXWIN 262144
#define MAXSEG (MAXWIN / SEG)
#define CSCSZ (WIN + (WIN >> 4) + 1)   // skewed LUT size (442 + 27)

typedef unsigned long long u64;

__device__ u64   g_csc[WIN];                 // packed (cos, -sin)
__device__ int   g_bins[MAXWIN];
__device__ __align__(16) unsigned g_mapsP[MAXSEG * NBINS];
__device__ int2  g_segin[MAXSEG];

// ---------------------------------------------------------------------------
// Twiddle LUT: csc[m] = (cos(2pi m/442), -sin(2pi m/442)) packed, fp32.
// ---------------------------------------------------------------------------
__global__ void k_init_tables() {
    int m = threadIdx.x;
    if (m < WIN) {
        double ang = (2.0 * 3.141592653589793238462643 * (double)m) / (double)WIN;
        float c = (float)cos(ang), s = (float)sin(ang);
        g_csc[m] = ((u64)__float_as_uint(-s) << 32) | (u64)__float_as_uint(c);
    }
}

// ---------------------------------------------------------------------------
// Packed f32x2 primitives (lane0 = re path, lane1 = im path). Componentwise
// RN rounding == scalar ops. Negation = sign XOR (alu pipe, exact).
// ---------------------------------------------------------------------------
__device__ __forceinline__ u64 pk2(float lo, float hi) {
    u64 r; asm("mov.b64 %0, {%1, %2};" : "=l"(r) : "f"(lo), "f"(hi)); return r;
}
__device__ __forceinline__ void upk2(u64 v, float& lo, float& hi) {
    asm("mov.b64 {%0, %1}, %2;" : "=f"(lo), "=f"(hi) : "l"(v));
}
__device__ __forceinline__ u64 fma2(u64 a, u64 b, u64 c) {
    u64 r; asm("fma.rn.f32x2 %0, %1, %2, %3;" : "=l"(r) : "l"(a), "l"(b), "l"(c)); return r;
}
__device__ __forceinline__ u64 add2(u64 a, u64 b) {
    u64 r; asm("add.rn.f32x2 %0, %1, %2;" : "=l"(r) : "l"(a), "l"(b)); return r;
}
__device__ __forceinline__ u64 mul2(u64 a, u64 b) {
    u64 r; asm("mul.rn.f32x2 %0, %1, %2;" : "=l"(r) : "l"(a), "l"(b)); return r;
}
__device__ __forceinline__ u64 neg2(u64 a) { return a ^ 0x8000000080000000ull; }

// Kahan with NEGATED compensation NC = -C (bit-identical to classic Kahan:
// y = P - C == P + NC; NC' = (S - t) + y == -((t - S) - y)). One neg2 only.
__device__ __forceinline__ void kaddn(u64& S, u64& NC, u64 P) {
    u64 y = add2(P, NC);
    u64 t = add2(S, y);
    NC = add2(add2(S, neg2(t)), y);
    S = t;
}

__device__ __forceinline__ unsigned redux_max_u32(unsigned v) {
    unsigned r;
    asm("redux.sync.max.u32 %0, %1, 0xffffffff;" : "=r"(r) : "r"(v));
    return r;
}

// skewed LUT index: breaks power-of-2-stride bank conflicts on the 8B table
__device__ __forceinline__ int sk(int m) { return m + (m >> 4); }

// ---------------------------------------------------------------------------
// DFT + argmax, rotation-free. One block = 576 windows, thread k = bin k.
// Y_w = W4^{-w} X_w accumulates ADDITIVELY (negated-Kahan f32x2):
//   Y_{w+1} = Y_w + sum_j d_j e^{-i th k (4w+j)}
// Magnitude via one non-accumulating fp32 rotation X_w = W4^{+w} Y_w, reusing
// the already-loaded csc[sk(idx0)]. Direct DFT of window 0 with the same
// 4-tap group structure. redux.sync argmax, ties -> lowest bin.
// ---------------------------------------------------------------------------
__global__ __launch_bounds__(224, 3) void k_dft(const float* __restrict__ x, int n_win) {
    __shared__ __align__(16) float xs[WIN + 4 * CWIN];   // 2746 floats
    __shared__ u64 csc[CSCSZ];
    __shared__ u64 wk[CWIN][7];

    const int tid = threadIdx.x;
    const int w0  = blockIdx.x * CWIN;
    const int nc  = min(CWIN, n_win - w0);
    const int s0  = w0 * HOP;
    const int L   = 4 * nc + 438;

    for (int i = tid; i < L; i += blockDim.x) xs[i] = x[s0 + i];
    for (int i = tid; i < WIN; i += blockDim.x) csc[sk(i)] = g_csc[i];
    __syncthreads();

    const int k    = tid;
    const int lane = tid & 31;
    const int wid  = tid >> 5;
    const bool act = (k < NBINS);

    const int step = (4 * k) % WIN;
    const int j1   = k % WIN;
    const int j2   = (2 * k) % WIN;
    const int j3   = (3 * k) % WIN;

    int idx0 = 0, idx1 = j1, idx2 = j2, idx3 = j3;
    u64 YH = 0ull, NC = 0ull;                   // Kahan (sum, negated comp)

    // ---- direct DFT of window 0: Y_0 = sum_n x_n (cos - i sin)(nk) ----
    #pragma unroll 2
    for (int g = 0; g < 110; g++) {
        const float4 xv = *(const float4*)&xs[4 * g];
        u64 T0 = csc[sk(idx0)], T1 = csc[sk(idx1)];
        u64 T2 = csc[sk(idx2)], T3 = csc[sk(idx3)];
        u64 P = add2(fma2(pk2(xv.y, xv.y), T1, mul2(pk2(xv.x, xv.x), T0)),
                     fma2(pk2(xv.w, xv.w), T3, mul2(pk2(xv.z, xv.z), T2)));
        kaddn(YH, NC, P);
        idx0 += step; if (idx0 >= WIN) idx0 -= WIN;
        idx1 += step; if (idx1 >= WIN) idx1 -= WIN;
        idx2 += step; if (idx2 >= WIN) idx2 -= WIN;
        idx3 += step; if (idx3 >= WIN) idx3 -= WIN;
    }
    {   // tail taps n = 440, 441
        float x0 = xs[440], x1 = xs[441];
        u64 P = fma2(pk2(x1, x1), csc[sk(idx1)], mul2(pk2(x0, x0), csc[sk(idx0)]));
        kaddn(YH, NC, P);
    }
    // reset counters for the slide phase (window 0 frame)
    idx0 = 0; idx1 = j1; idx2 = j2; idx3 = j3;

    #pragma unroll 2
    for (int w = 0; w < nc; w++) {
        u64 T0 = csc[sk(idx0)];                 // shared by mag + slide

        // ---- magnitude of X_w = W4^{+w} Y_w, with Y corrected = YH + NC
        u64 Yc = add2(YH, NC);
        float yr, yi, tc, nsn;                  // nsn = -sin
        upk2(Yc, yr, yi);
        upk2(T0, tc, nsn);
        float xr = __fmaf_rn(yi, nsn, __fmul_rn(yr, tc));   // yr c - yi s
        float tt = __fmul_rn(yr, nsn);
        float xi = __fmaf_rn(yi, tc, -tt);                  // yr s + yi c
        float mag = __fadd_rn(fabsf(xr), fabsf(xi));
        unsigned mbits = act ? __float_as_uint(mag) : 0u;

        unsigned mx = redux_max_u32(mbits);
        unsigned eq = __ballot_sync(0xffffffffu, mbits == mx);
        if (lane == 0) {
            unsigned bin = (unsigned)(wid * 32 + (__ffs(eq) - 1));
            wk[w][wid] = (((u64)mx) << 32) | (u64)(0xFFFFFFFFu - bin);
        }

        // ---- slide: Y += sum_j d_j e^{-i th k (4w+j)}
        if (w + 1 < nc) {
            const int p = 4 * w;
            const float4 a  = *(const float4*)&xs[p];
            const float2 b0 = *(const float2*)&xs[p + 442];
            const float2 b1 = *(const float2*)&xs[p + 444];
            float d0 = __fsub_rn(b0.x, a.x);
            float d1 = __fsub_rn(b0.y, a.y);
            float d2 = __fsub_rn(b1.x, a.z);
            float d3 = __fsub_rn(b1.y, a.w);
            u64 T1 = csc[sk(idx1)], T2 = csc[sk(idx2)], T3 = csc[sk(idx3)];
            u64 D = add2(fma2(pk2(d1, d1), T1, mul2(pk2(d0, d0), T0)),
                         fma2(pk2(d3, d3), T3, mul2(pk2(d2, d2), T2)));
            kaddn(YH, NC, D);
            idx0 += step; if (idx0 >= WIN) idx0 -= WIN;
            idx1 += step; if (idx1 >= WIN) idx1 -= WIN;
            idx2 += step; if (idx2 >= WIN) idx2 -= WIN;
            idx3 += step; if (idx3 >= WIN) idx3 -= WIN;
        }
    }
    __syncthreads();

    for (int i = tid; i < nc; i += blockDim.x) {
        u64 m = wk[i][0];
        #pragma unroll
        for (int j = 1; j < 7; j++) if (wk[i][j] > m) m = wk[i][j];
        g_bins[w0 + i] = (int)(0xFFFFFFFFu - (unsigned)(m & 0xFFFFFFFFull));
    }
}

// ---------------------------------------------------------------------------
// Scan phase 1: per-segment transition maps, written PACKED:
// (global_reset_time << 8) | bin, sentinel 0xFFFFFFFF = state survives.
// ---------------------------------------------------------------------------
__global__ void k_segmaps(int n_win) {
    __shared__ int   sb[SEG];
    __shared__ short sj[SEG];
    const int seg = blockIdx.x;
    const int s0  = seg * SEG;
    const int len = min(SEG, n_win - s0);

    for (int i = threadIdx.x; i < SEG; i += blockDim.x)
        sb[i] = (i < len) ? g_bins[s0 + i] : 0;
    __syncthreads();

    for (int p = threadIdx.x; p < len; p += blockDim.x) {
        float F   = 100.0f * (float)sb[p];
        float thr = F * RELC;
        int j = p + 1;
        while (j < len && fabsf(F - 100.0f * (float)sb[j]) <= thr) j++;
        sj[p] = (short)((j < len) ? j : p);      // self-loop == terminal
    }
    __syncthreads();

    for (int r = 0; r < 11; r++) {               // log2(2048) rounds
        for (int p = threadIdx.x; p < len; p += blockDim.x)
            sj[p] = sj[sj[p]];
        __syncthreads();
    }

    for (int f = threadIdx.x; f < NBINS; f += blockDim.x) {
        float F   = 100.0f * (float)f;
        float thr = F * RELC;
        int j = 0;
        while (j < len && fabsf(F - 100.0f * (float)sb[j]) <= thr) j++;
        unsigned v;
        if (j >= len) v = 0xFFFFFFFFu;
        else { int term = sj[j]; v = (((unsigned)(s0 + term)) << 8) | (unsigned)sb[term]; }
        g_mapsP[seg * NBINS + f] = v;
    }
}

// ---------------------------------------------------------------------------
// Scan phase 2: bulk-load packed maps (108 KB) with wide uint4 loads and
// 1024 threads (deep MLP), then thread 0 walks the chain in shared memory.
// ---------------------------------------------------------------------------
__global__ void k_walk(int n_win, int nseg, float* __restrict__ out) {
    extern __shared__ unsigned sm[];
    const int tot  = nseg * NBINS;
    const int tot4 = tot >> 2;
    const uint4* src4 = (const uint4*)g_mapsP;
    uint4* dst4 = (uint4*)sm;
    for (int i = threadIdx.x; i < tot4; i += blockDim.x) dst4[i] = src4[i];
    for (int i = (tot4 << 2) + threadIdx.x; i < tot; i += blockDim.x) sm[i] = g_mapsP[i];
    __syncthreads();

    if (threadIdx.x == 0) {
        int bF = 0, Tw = 0;
        for (int s = 0; s < nseg; s++) {
            g_segin[s] = make_int2(bF, Tw);
            unsigned v = sm[s * NBINS + bF];
            if (v != 0xFFFFFFFFu) { bF = (int)(v & 0xFFu); Tw = (int)(v >> 8); }
        }
        float F    = 100.0f * (float)bF;
        float Ft   = 4.0f * (float)Tw;
        float last = 4.0f * (float)(n_win - 1);
        out[3 * n_win + 0] = F;
        out[3 * n_win + 1] = __fdiv_rn((last - Ft) * 1000.0f, 44100.0f);
    }
}

// ---------------------------------------------------------------------------
// Scan phase 3: parallel fill. One warp per segment replays the exact
// reference emit semantics (cond/emit use PRE-update state) via ballots.
// ---------------------------------------------------------------------------
__global__ void k_fill(int n_win, float* __restrict__ out) {
    const int seg = blockIdx.x;
    const int s0  = seg * SEG;
    const int len = min(SEG, n_win - s0);
    const int lane = threadIdx.x;

    int2 st0 = g_segin[seg];
    float F = 100.0f * (float)st0.x;
    float T = 4.0f * (float)st0.y;

    float* flags = out;
    float* freqs = out + n_win;
    float* durs  = out + 2 * n_win;

    for (int base = 0; base < len; base += 32) {
        int  i     = s0 + base + lane;
        bool valid = (base + lane) < len;
        float t = valid ? 100.0f * (float)g_bins[i] : 0.0f;

        unsigned rem = __ballot_sync(0xffffffffu, valid);
        float myF = 0.f, myT = 0.f;
        bool  myc = false;
        while (rem) {
            bool oob = fabsf(F - t) > F * RELC;
            unsigned bal = __ballot_sync(0xffffffffu, oob) & rem;
            if (!bal) {
                if (rem & (1u << lane)) { myF = F; myT = T; }
                break;
            }
            int e = __ffs(bal) - 1;
            if ((rem & (1u << lane)) && lane <= e) {
                myF = F; myT = T; myc = (lane == e);
            }
            F = __shfl_sync(0xffffffffu, t, e);
            T = 4.0f * (float)(s0 + base + e);
            unsigned below = (e == 31) ? 0xffffffffu : ((1u << (e + 1)) - 1u);
            rem &= ~below;
        }
        if (valid) {
            flags[i] = myc ? 1.0f : 0.0f;
            freqs[i] = myF;
            durs[i]  = __fdiv_rn(((float)(4 * i) - myT) * 1000.0f, 44100.0f);
        }
    }
}

// ---------------------------------------------------------------------------
extern "C" void kernel_launch(void* const* d_in, const int* in_sizes, int n_in,
                              void* d_out, int out_size) {
    const float* x = (const float*)d_in[0];
    int n     = in_sizes[0];
    int n_win = (n - WIN + HOP - 1) / HOP;
    if (n_win > MAXWIN) n_win = MAXWIN;   // safety cap (fixed input: 249890)
    int nblk = (n_win + CWIN - 1) / CWIN;
    int nseg = (n_win + SEG - 1) / SEG;
    float* out = (float*)d_out;

    size_t walk_smem = (size_t)nseg * NBINS * sizeof(unsigned);  // ~108.7 KB
    static bool attr_done = false;
    if (!attr_done) {
        cudaFuncSetAttribute(k_walk, cudaFuncAttributeMaxDynamicSharedMemorySize,
                             (int)(116 * 1024));
        attr_done = true;
    }

    k_init_tables<<<1, 448>>>();
    k_dft<<<nblk, 224>>>(x, n_win);
    k_segmaps<<<nseg, 256>>>(n_win);
    k_walk<<<1, 1024, walk_smem>>>(n_win, nseg, out);
    k_fill<<<nseg, 32>>>(n_win, out);
}

// round 9
// speedup vs baseline: 1.5360x; 1.0119x over previous
#include <cuda_runtime.h>
#include <stdint.h>

#define WIN   442
#define NBINS 221
#define HOP   4
#define RELC  0.0594f
#define CWIN  432           // 579 blocks -> ONE wave at 4 blocks/SM (592 slots)
#define SEG   2048          // windows per scan segment
#define MAXWIN 262144
#define MAXSEG (MAXWIN / SEG)
#define CSCSZ (WIN + (WIN >> 4) + 1)   // skewed LUT size (442 + 27)

typedef unsigned long long u64;

__device__ u64   g_csc[WIN];                 // packed (cos, -sin)
__device__ int   g_bins[MAXWIN];
__device__ __align__(16) unsigned g_mapsP[MAXSEG * NBINS];
__device__ int2  g_segin[MAXSEG];

// ---------------------------------------------------------------------------
// Twiddle LUT: csc[m] = (cos(2pi m/442), -sin(2pi m/442)) packed, fp32.
// ---------------------------------------------------------------------------
__global__ void k_init_tables() {
    int m = threadIdx.x;
    if (m < WIN) {
        double ang = (2.0 * 3.141592653589793238462643 * (double)m) / (double)WIN;
        float c = (float)cos(ang), s = (float)sin(ang);
        g_csc[m] = ((u64)__float_as_uint(-s) << 32) | (u64)__float_as_uint(c);
    }
}

// ---------------------------------------------------------------------------
// Packed f32x2 primitives (lane0 = re path, lane1 = im path). Componentwise
// RN rounding == scalar ops. Negation = sign XOR (alu pipe, exact).
// ---------------------------------------------------------------------------
__device__ __forceinline__ u64 pk2(float lo, float hi) {
    u64 r; asm("mov.b64 %0, {%1, %2};" : "=l"(r) : "f"(lo), "f"(hi)); return r;
}
__device__ __forceinline__ void upk2(u64 v, float& lo, float& hi) {
    asm("mov.b64 {%0, %1}, %2;" : "=f"(lo), "=f"(hi) : "l"(v));
}
__device__ __forceinline__ u64 fma2(u64 a, u64 b, u64 c) {
    u64 r; asm("fma.rn.f32x2 %0, %1, %2, %3;" : "=l"(r) : "l"(a), "l"(b), "l"(c)); return r;
}
__device__ __forceinline__ u64 add2(u64 a, u64 b) {
    u64 r; asm("add.rn.f32x2 %0, %1, %2;" : "=l"(r) : "l"(a), "l"(b)); return r;
}
__device__ __forceinline__ u64 mul2(u64 a, u64 b) {
    u64 r; asm("mul.rn.f32x2 %0, %1, %2;" : "=l"(r) : "l"(a), "l"(b)); return r;
}
__device__ __forceinline__ u64 neg2(u64 a) { return a ^ 0x8000000080000000ull; }

// Kahan with NEGATED compensation NC = -C (bit-identical to classic Kahan:
// y = P - C == P + NC; NC' = (S - t) + y == -((t - S) - y)). One neg2 only.
__device__ __forceinline__ void kaddn(u64& S, u64& NC, u64 P) {
    u64 y = add2(P, NC);
    u64 t = add2(S, y);
    NC = add2(add2(S, neg2(t)), y);
    S = t;
}

__device__ __forceinline__ unsigned redux_max_u32(unsigned v) {
    unsigned r;
    asm("redux.sync.max.u32 %0, %1, 0xffffffff;" : "=r"(r) : "r"(v));
    return r;
}

// skewed LUT index: breaks power-of-2-stride bank conflicts on the 8B table
__device__ __forceinline__ int sk(int m) { return m + (m >> 4); }

// ---------------------------------------------------------------------------
// DFT + argmax, rotation-free. One block = 432 windows, thread -> bin
// kk = min(tid, 220): the 3 tail threads duplicate bin 220 (a duplicate can
// never beat the true lane in the tie-break: equality ballot picks the
// LOWEST lane, which is the genuine bin-220 lane). Y_w = W4^{-w} X_w
// accumulates ADDITIVELY (negated-Kahan f32x2):
//   Y_{w+1} = Y_w + sum_j d_j e^{-i th k (4w+j)}
// Magnitude via one non-accumulating fp32 rotation X_w = W4^{+w} Y_w reusing
// csc[sk(idx0)]. Direct DFT of window 0 with the same 4-tap group structure.
// redux.sync argmax, ties -> lowest bin (matches jnp.argmax).
// ---------------------------------------------------------------------------
__global__ __launch_bounds__(224, 4) void k_dft(const float* __restrict__ x, int n_win) {
    __shared__ __align__(16) float xs[WIN + 4 * CWIN];   // 2170 floats
    __shared__ u64 csc[CSCSZ];
    __shared__ u64 wk[CWIN][7];

    const int tid = threadIdx.x;
    const int w0  = blockIdx.x * CWIN;
    const int nc  = min(CWIN, n_win - w0);
    const int s0  = w0 * HOP;
    const int L   = 4 * nc + 438;

    for (int i = tid; i < L; i += blockDim.x) xs[i] = x[s0 + i];
    for (int i = tid; i < WIN; i += blockDim.x) csc[sk(i)] = g_csc[i];
    __syncthreads();

    const int kk   = min(tid, NBINS - 1);       // clamp: tail lanes dup bin 220
    const int lane = tid & 31;
    const int wid  = tid >> 5;

    const int step = (4 * kk) % WIN;
    const int j1   = kk;
    const int j2   = (2 * kk) % WIN;
    const int j3   = (3 * kk) % WIN;

    int idx0 = 0, idx1 = j1, idx2 = j2, idx3 = j3;
    u64 YH = 0ull, NC = 0ull;                   // Kahan (sum, negated comp)

    // ---- direct DFT of window 0: Y_0 = sum_n x_n (cos - i sin)(nk) ----
    #pragma unroll 2
    for (int g = 0; g < 110; g++) {
        const float4 xv = *(const float4*)&xs[4 * g];
        u64 T0 = csc[sk(idx0)], T1 = csc[sk(idx1)];
        u64 T2 = csc[sk(idx2)], T3 = csc[sk(idx3)];
        u64 P = add2(fma2(pk2(xv.y, xv.y), T1, mul2(pk2(xv.x, xv.x), T0)),
                     fma2(pk2(xv.w, xv.w), T3, mul2(pk2(xv.z, xv.z), T2)));
        kaddn(YH, NC, P);
        idx0 += step; if (idx0 >= WIN) idx0 -= WIN;
        idx1 += step; if (idx1 >= WIN) idx1 -= WIN;
        idx2 += step; if (idx2 >= WIN) idx2 -= WIN;
        idx3 += step; if (idx3 >= WIN) idx3 -= WIN;
    }
    {   // tail taps n = 440, 441
        float x0 = xs[440], x1 = xs[441];
        u64 P = fma2(pk2(x1, x1), csc[sk(idx1)], mul2(pk2(x0, x0), csc[sk(idx0)]));
        kaddn(YH, NC, P);
    }
    // reset counters for the slide phase (window 0 frame)
    idx0 = 0; idx1 = j1; idx2 = j2; idx3 = j3;

    #pragma unroll 2
    for (int w = 0; w < nc; w++) {
        u64 T0 = csc[sk(idx0)];                 // shared by mag + slide

        // ---- magnitude of X_w = W4^{+w} Y_w, with Y corrected = YH + NC
        u64 Yc = add2(YH, NC);
        float yr, yi, tc, nsn;                  // nsn = -sin
        upk2(Yc, yr, yi);
        upk2(T0, tc, nsn);
        float xr = __fmaf_rn(yi, nsn, __fmul_rn(yr, tc));   // yr c - yi s
        float tt = __fmul_rn(yr, nsn);
        float xi = __fmaf_rn(yi, tc, -tt);                  // yr s + yi c
        float mag = __fadd_rn(fabsf(xr), fabsf(xi));
        unsigned mbits = __float_as_uint(mag);

        unsigned mx = redux_max_u32(mbits);
        unsigned eq = __ballot_sync(0xffffffffu, mbits == mx);
        if (lane == 0) {
            unsigned bin = (unsigned)(wid * 32 + (__ffs(eq) - 1));
            wk[w][wid] = (((u64)mx) << 32) | (u64)(0xFFFFFFFFu - bin);
        }

        // ---- slide: Y += sum_j d_j e^{-i th k (4w+j)}
        if (w + 1 < nc) {
            const int p = 4 * w;
            const float4 a  = *(const float4*)&xs[p];
            const float2 b0 = *(const float2*)&xs[p + 442];
            const float2 b1 = *(const float2*)&xs[p + 444];
            float d0 = __fsub_rn(b0.x, a.x);
            float d1 = __fsub_rn(b0.y, a.y);
            float d2 = __fsub_rn(b1.x, a.z);
            float d3 = __fsub_rn(b1.y, a.w);
            u64 T1 = csc[sk(idx1)], T2 = csc[sk(idx2)], T3 = csc[sk(idx3)];
            u64 D = add2(fma2(pk2(d1, d1), T1, mul2(pk2(d0, d0), T0)),
                         fma2(pk2(d3, d3), T3, mul2(pk2(d2, d2), T2)));
            kaddn(YH, NC, D);
            idx0 += step; if (idx0 >= WIN) idx0 -= WIN;
            idx1 += step; if (idx1 >= WIN) idx1 -= WIN;
            idx2 += step; if (idx2 >= WIN) idx2 -= WIN;
            idx3 += step; if (idx3 >= WIN) idx3 -= WIN;
        }
    }
    __syncthreads();

    for (int i = tid; i < nc; i += blockDim.x) {
        u64 m = wk[i][0];
        #pragma unroll
        for (int j = 1; j < 7; j++) if (wk[i][j] > m) m = wk[i][j];
        g_bins[w0 + i] = (int)(0xFFFFFFFFu - (unsigned)(m & 0xFFFFFFFFull));
    }
}

// ---------------------------------------------------------------------------
// Scan phase 1: per-segment transition maps, written PACKED:
// (global_reset_time << 8) | bin, sentinel 0xFFFFFFFF = state survives.
// ---------------------------------------------------------------------------
__global__ void k_segmaps(int n_win) {
    __shared__ int   sb[SEG];
    __shared__ short sj[SEG];
    const int seg = blockIdx.x;
    const int s0  = seg * SEG;
    const int len = min(SEG, n_win - s0);

    for (int i = threadIdx.x; i < SEG; i += blockDim.x)
        sb[i] = (i < len) ? g_bins[s0 + i] : 0;
    __syncthreads();

    for (int p = threadIdx.x; p < len; p += blockDim.x) {
        float F   = 100.0f * (float)sb[p];
        float thr = F * RELC;
        int j = p + 1;
        while (j < len && fabsf(F - 100.0f * (float)sb[j]) <= thr) j++;
        sj[p] = (short)((j < len) ? j : p);      // self-loop == terminal
    }
    __syncthreads();

    for (int r = 0; r < 11; r++) {               // log2(2048) rounds
        for (int p = threadIdx.x; p < len; p += blockDim.x)
            sj[p] = sj[sj[p]];
        __syncthreads();
    }

    for (int f = threadIdx.x; f < NBINS; f += blockDim.x) {
        float F   = 100.0f * (float)f;
        float thr = F * RELC;
        int j = 0;
        while (j < len && fabsf(F - 100.0f * (float)sb[j]) <= thr) j++;
        unsigned v;
        if (j >= len) v = 0xFFFFFFFFu;
        else { int term = sj[j]; v = (((unsigned)(s0 + term)) << 8) | (unsigned)sb[term]; }
        g_mapsP[seg * NBINS + f] = v;
    }
}

// ---------------------------------------------------------------------------
// Scan phase 2: bulk-load packed maps (108 KB) with wide uint4 loads and
// 1024 threads (deep MLP), then thread 0 walks the chain in shared memory.
// ---------------------------------------------------------------------------
__global__ void k_walk(int n_win, int nseg, float* __restrict__ out) {
    extern __shared__ unsigned sm[];
    const int tot  = nseg * NBINS;
    const int tot4 = tot >> 2;
    const uint4* src4 = (const uint4*)g_mapsP;
    uint4* dst4 = (uint4*)sm;
    for (int i = threadIdx.x; i < tot4; i += blockDim.x) dst4[i] = src4[i];
    for (int i = (tot4 << 2) + threadIdx.x; i < tot; i += blockDim.x) sm[i] = g_mapsP[i];
    __syncthreads();

    if (threadIdx.x == 0) {
        int bF = 0, Tw = 0;
        for (int s = 0; s < nseg; s++) {
            g_segin[s] = make_int2(bF, Tw);
            unsigned v = sm[s * NBINS + bF];
            if (v != 0xFFFFFFFFu) { bF = (int)(v & 0xFFu); Tw = (int)(v >> 8); }
        }
        float F    = 100.0f * (float)bF;
        float Ft   = 4.0f * (float)Tw;
        float last = 4.0f * (float)(n_win - 1);
        out[3 * n_win + 0] = F;
        out[3 * n_win + 1] = __fdiv_rn((last - Ft) * 1000.0f, 44100.0f);
    }
}

// ---------------------------------------------------------------------------
// Scan phase 3: parallel fill. One warp per segment replays the exact
// reference emit semantics (cond/emit use PRE-update state) via ballots.
// ---------------------------------------------------------------------------
__global__ void k_fill(int n_win, float* __restrict__ out) {
    const int seg = blockIdx.x;
    const int s0  = seg * SEG;
    const int len = min(SEG, n_win - s0);
    const int lane = threadIdx.x;

    int2 st0 = g_segin[seg];
    float F = 100.0f * (float)st0.x;
    float T = 4.0f * (float)st0.y;

    float* flags = out;
    float* freqs = out + n_win;
    float* durs  = out + 2 * n_win;

    for (int base = 0; base < len; base += 32) {
        int  i     = s0 + base + lane;
        bool valid = (base + lane) < len;
        float t = valid ? 100.0f * (float)g_bins[i] : 0.0f;

        unsigned rem = __ballot_sync(0xffffffffu, valid);
        float myF = 0.f, myT = 0.f;
        bool  myc = false;
        while (rem) {
            bool oob = fabsf(F - t) > F * RELC;
            unsigned bal = __ballot_sync(0xffffffffu, oob) & rem;
            if (!bal) {
                if (rem & (1u << lane)) { myF = F; myT = T; }
                break;
            }
            int e = __ffs(bal) - 1;
            if ((rem & (1u << lane)) && lane <= e) {
                myF = F; myT = T; myc = (lane == e);
            }
            F = __shfl_sync(0xffffffffu, t, e);
            T = 4.0f * (float)(s0 + base + e);
            unsigned below = (e == 31) ? 0xffffffffu : ((1u << (e + 1)) - 1u);
            rem &= ~below;
        }
        if (valid) {
            flags[i] = myc ? 1.0f : 0.0f;
            freqs[i] = myF;
            durs[i]  = __fdiv_rn(((float)(4 * i) - myT) * 1000.0f, 44100.0f);
        }
    }
}

// ---------------------------------------------------------------------------
extern "C" void kernel_launch(void* const* d_in, const int* in_sizes, int n_in,
                              void* d_out, int out_size) {
    const float* x = (const float*)d_in[0];
    int n     = in_sizes[0];
    int n_win = (n - WIN + HOP - 1) / HOP;
    if (n_win > MAXWIN) n_win = MAXWIN;   // safety cap (fixed input: 249890)
    int nblk = (n_win + CWIN - 1) / CWIN;
    int nseg = (n_win + SEG - 1) / SEG;
    float* out = (float*)d_out;

    size_t walk_smem = (size_t)nseg * NBINS * sizeof(unsigned);  // ~108.7 KB
    static bool attr_done = false;
    if (!attr_done) {
        cudaFuncSetAttribute(k_walk, cudaFuncAttributeMaxDynamicSharedMemorySize,
                             (int)(116 * 1024));
        attr_done = true;
    }

    k_init_tables<<<1, 448>>>();
    k_dft<<<nblk, 224>>>(x, n_win);
    k_segmaps<<<nseg, 256>>>(n_win);
    k_walk<<<1, 1024, walk_smem>>>(n_win, nseg, out);
    k_fill<<<nseg, 32>>>(n_win, out);
}

// round 10
// speedup vs baseline: 1.8828x; 1.2258x over previous
#include <cuda_runtime.h>
#include <stdint.h>

#define WIN   442
#define NBINS 221
#define HOP   4
#define RELC  0.0594f
#define CWIN  432           // 579 blocks -> ONE wave at 4 blocks/SM
#define BATW  36            // windows per argmax batch (432 = 12 * 36)
#define RS    229           // mags row stride (229 mod 32 = 5, conflict-free)
#define SEG   2048          // windows per scan segment
#define MAXWIN 262144
#define MAXSEG (MAXWIN / SEG)
#define CSCSZ (WIN + (WIN >> 4) + 1)   // skewed LUT size (442 + 27)

typedef unsigned long long u64;

__device__ u64   g_csc[WIN];                 // packed (cos, -sin)
__device__ int   g_bins[MAXWIN];
__device__ __align__(16) unsigned g_mapsP[MAXSEG * NBINS];
__device__ int2  g_segin[MAXSEG];

// ---------------------------------------------------------------------------
// Twiddle LUT: csc[m] = (cos(2pi m/442), -sin(2pi m/442)) packed, fp32.
// ---------------------------------------------------------------------------
__global__ void k_init_tables() {
    int m = threadIdx.x;
    if (m < WIN) {
        double ang = (2.0 * 3.141592653589793238462643 * (double)m) / (double)WIN;
        float c = (float)cos(ang), s = (float)sin(ang);
        g_csc[m] = ((u64)__float_as_uint(-s) << 32) | (u64)__float_as_uint(c);
    }
}

// ---------------------------------------------------------------------------
// Packed f32x2 primitives (lane0 = re, lane1 = im). Componentwise RN.
// ---------------------------------------------------------------------------
__device__ __forceinline__ u64 pk2(float lo, float hi) {
    u64 r; asm("mov.b64 %0, {%1, %2};" : "=l"(r) : "f"(lo), "f"(hi)); return r;
}
__device__ __forceinline__ void upk2(u64 v, float& lo, float& hi) {
    asm("mov.b64 {%0, %1}, %2;" : "=f"(lo), "=f"(hi) : "l"(v));
}
__device__ __forceinline__ u64 add2(u64 a, u64 b) {
    u64 r; asm("add.rn.f32x2 %0, %1, %2;" : "=l"(r) : "l"(a), "l"(b)); return r;
}
__device__ __forceinline__ u64 neg2(u64 a) { return a ^ 0x8000000080000000ull; }

// Kahan with negated compensation NC = -C (bit-identical to classic Kahan).
__device__ __forceinline__ void kaddn(u64& S, u64& NC, u64 P) {
    u64 y = add2(P, NC);
    u64 t = add2(S, y);
    NC = add2(add2(S, neg2(t)), y);
    S = t;
}

// skewed LUT index: breaks power-of-2-stride bank conflicts on the 8B table
__device__ __forceinline__ int sk(int m) { return m + (m >> 4); }

// ---------------------------------------------------------------------------
// DFT + argmax, rotation-free + twiddle-factored. One block = 432 windows,
// thread -> bin kk = min(tid, 220) (dup lanes write cols 221..223, ignored).
// Y_w = W4^{-w} X_w accumulates additively (negated-Kahan f32x2):
//   Y_{w+1} = Y_w + T0_w * (d0 + d1 E1 + d2 E2 + d3 E3),
// with T0_w = e^{-i th k 4w} = csc[idx0] (shared with the magnitude rotation)
// and E_j = e^{-i th k j} per-thread register constants. Magnitude via one
// non-accumulating rotation X_w = conj(T0_w) * Y. Argmax is BATCHED: mags go
// to smem (36 windows), then 216 threads reduce (window, bin-sixth) slices
// with strict > ascending (ties -> lowest bin, matching jnp.argmax), merged
// via packed-key u64 max.
// ---------------------------------------------------------------------------
__global__ __launch_bounds__(224, 4) void k_dft(const float* __restrict__ x, int n_win) {
    __shared__ __align__(16) float xs[WIN + 4 * CWIN];   // 2170 floats
    __shared__ u64   csc[CSCSZ];
    __shared__ float mags[BATW * RS];                    // 36 x 229
    __shared__ u64   pkeys[BATW * 7];

    const int tid = threadIdx.x;
    const int w0  = blockIdx.x * CWIN;
    const int nc  = min(CWIN, n_win - w0);
    const int s0  = w0 * HOP;
    const int L   = 4 * nc + 438;

    for (int i = tid; i < L; i += blockDim.x) xs[i] = x[s0 + i];
    for (int i = tid; i < WIN; i += blockDim.x) csc[sk(i)] = g_csc[i];
    __syncthreads();

    const int kk = min(tid, NBINS - 1);       // clamp: tail lanes dup bin 220
    const int step = (4 * kk) % WIN;

    // per-thread twiddle constants E_j = (cos(j th k), -sin(j th k))
    float e1r, e1i, e2r, e2i, e3r, e3i;
    upk2(csc[sk(kk)], e1r, e1i);
    upk2(csc[sk((2 * kk) % WIN)], e2r, e2i);
    upk2(csc[sk((3 * kk) % WIN)], e3r, e3i);

    int idx0 = 0;
    u64 YH = 0ull, NC = 0ull;                 // Kahan (sum, negated comp)

    // ---- direct DFT of window 0: groups of 4 taps, factored twiddles ----
    #pragma unroll 2
    for (int g = 0; g < 110; g++) {
        const float4 xv = *(const float4*)&xs[4 * g];
        float tc, nsn;  upk2(csc[sk(idx0)], tc, nsn);
        float Zr = __fmaf_rn(xv.w, e3r, __fmaf_rn(xv.z, e2r, __fmaf_rn(xv.y, e1r, xv.x)));
        float Zi = __fmaf_rn(xv.w, e3i, __fmaf_rn(xv.z, e2i, __fmul_rn(xv.y, e1i)));
        float Dre = __fmaf_rn(-Zi, nsn, __fmul_rn(Zr, tc));
        float Dim = __fmaf_rn( Zi, tc,  __fmul_rn(Zr, nsn));
        kaddn(YH, NC, pk2(Dre, Dim));
        idx0 += step; if (idx0 >= WIN) idx0 -= WIN;
    }
    {   // tail taps n = 440, 441 (idx0 = 440k mod 442 here)
        float tc, nsn;  upk2(csc[sk(idx0)], tc, nsn);
        float x0 = xs[440], x1 = xs[441];
        float Zr = __fmaf_rn(x1, e1r, x0);
        float Zi = __fmul_rn(x1, e1i);
        float Dre = __fmaf_rn(-Zi, nsn, __fmul_rn(Zr, tc));
        float Dim = __fmaf_rn( Zi, tc,  __fmul_rn(Zr, nsn));
        kaddn(YH, NC, pk2(Dre, Dim));
    }
    idx0 = 0;                                  // window-0 frame for slides

    for (int b0 = 0; b0 < nc; b0 += BATW) {
        const int bw = min(BATW, nc - b0);

        // ---- phase 1: compute mags for bw windows, slide between them ----
        float* mrow = &mags[tid];
        for (int w = b0; w < b0 + bw; w++) {
            float tc, nsn;  upk2(csc[sk(idx0)], tc, nsn);   // T0_w

            u64 Yc = add2(YH, NC);
            float yr, yi;  upk2(Yc, yr, yi);
            float xr = __fmaf_rn(yi, nsn, __fmul_rn(yr, tc));
            float xi = __fmaf_rn(yi, tc, -__fmul_rn(yr, nsn));
            mrow[(w - b0) * RS] = __fadd_rn(fabsf(xr), fabsf(xi));

            if (w + 1 < nc) {
                const int p = 4 * w;
                const float4 a  = *(const float4*)&xs[p];
                const float2 v0 = *(const float2*)&xs[p + 442];
                const float2 v1 = *(const float2*)&xs[p + 444];
                float d0 = __fsub_rn(v0.x, a.x);
                float d1 = __fsub_rn(v0.y, a.y);
                float d2 = __fsub_rn(v1.x, a.z);
                float d3 = __fsub_rn(v1.y, a.w);
                float Zr = __fmaf_rn(d3, e3r, __fmaf_rn(d2, e2r, __fmaf_rn(d1, e1r, d0)));
                float Zi = __fmaf_rn(d3, e3i, __fmaf_rn(d2, e2i, __fmul_rn(d1, e1i)));
                float Dre = __fmaf_rn(-Zi, nsn, __fmul_rn(Zr, tc));
                float Dim = __fmaf_rn( Zi, tc,  __fmul_rn(Zr, nsn));
                kaddn(YH, NC, pk2(Dre, Dim));
                idx0 += step; if (idx0 >= WIN) idx0 -= WIN;
            }
        }
        __syncthreads();

        // ---- phase 2: per-window partial argmax over bin sixths ----
        {
            const int win  = tid % BATW;
            const int part = tid / BATW;         // 0..5 used (216 threads)
            if (part < 6 && win < bw) {
                const int kbeg = part * 37;
                const int kend = min(kbeg + 37, NBINS);
                const float* row = &mags[win * RS];
                float best = row[kbeg];
                int   bbin = kbeg;
                for (int kx = kbeg + 1; kx < kend; kx++) {
                    float v = row[kx];
                    if (v > best) { best = v; bbin = kx; }   // ties -> lower
                }
                pkeys[win * 7 + part] =
                    (((u64)__float_as_uint(best)) << 32)
                    | (u64)(0xFFFFFFFFu - (unsigned)bbin);
            }
        }
        __syncthreads();

        // ---- merge 6 partials per window (packed-key max: ties -> low bin)
        if (tid < bw) {
            u64 m = pkeys[tid * 7];
            #pragma unroll
            for (int j = 1; j < 6; j++) {
                u64 v = pkeys[tid * 7 + j];
                if (v > m) m = v;
            }
            g_bins[w0 + b0 + tid] = (int)(0xFFFFFFFFu - (unsigned)(m & 0xFFFFFFFFull));
        }
        // next phase-1 STS to mags is ordered after this batch's phase-2
        // reads by the syncthreads at the top of the next batch's phase 2;
        // pkeys writes are ordered after the merge by the phase-1 sync.
        __syncthreads();
    }
}

// ---------------------------------------------------------------------------
// Scan phase 1: per-segment transition maps, written PACKED:
// (global_reset_time << 8) | bin, sentinel 0xFFFFFFFF = state survives.
// ---------------------------------------------------------------------------
__global__ void k_segmaps(int n_win) {
    __shared__ int   sb[SEG];
    __shared__ short sj[SEG];
    const int seg = blockIdx.x;
    const int s0  = seg * SEG;
    const int len = min(SEG, n_win - s0);

    for (int i = threadIdx.x; i < SEG; i += blockDim.x)
        sb[i] = (i < len) ? g_bins[s0 + i] : 0;
    __syncthreads();

    for (int p = threadIdx.x; p < len; p += blockDim.x) {
        float F   = 100.0f * (float)sb[p];
        float thr = F * RELC;
        int j = p + 1;
        while (j < len && fabsf(F - 100.0f * (float)sb[j]) <= thr) j++;
        sj[p] = (short)((j < len) ? j : p);      // self-loop == terminal
    }
    __syncthreads();

    for (int r = 0; r < 11; r++) {               // log2(2048) rounds
        for (int p = threadIdx.x; p < len; p += blockDim.x)
            sj[p] = sj[sj[p]];
        __syncthreads();
    }

    for (int f = threadIdx.x; f < NBINS; f += blockDim.x) {
        float F   = 100.0f * (float)f;
        float thr = F * RELC;
        int j = 0;
        while (j < len && fabsf(F - 100.0f * (float)sb[j]) <= thr) j++;
        unsigned v;
        if (j >= len) v = 0xFFFFFFFFu;
        else { int term = sj[j]; v = (((unsigned)(s0 + term)) << 8) | (unsigned)sb[term]; }
        g_mapsP[seg * NBINS + f] = v;
    }
}

// ---------------------------------------------------------------------------
// Scan phase 2: bulk-load packed maps (108 KB) with wide uint4 loads and
// 1024 threads (deep MLP), then thread 0 walks the chain in shared memory.
// ---------------------------------------------------------------------------
__global__ void k_walk(int n_win, int nseg, float* __restrict__ out) {
    extern __shared__ unsigned sm[];
    const int tot  = nseg * NBINS;
    const int tot4 = tot >> 2;
    const uint4* src4 = (const uint4*)g_mapsP;
    uint4* dst4 = (uint4*)sm;
    for (int i = threadIdx.x; i < tot4; i += blockDim.x) dst4[i] = src4[i];
    for (int i = (tot4 << 2) + threadIdx.x; i < tot; i += blockDim.x) sm[i] = g_mapsP[i];
    __syncthreads();

    if (threadIdx.x == 0) {
        int bF = 0, Tw = 0;
        for (int s = 0; s < nseg; s++) {
            g_segin[s] = make_int2(bF, Tw);
            unsigned v = sm[s * NBINS + bF];
            if (v != 0xFFFFFFFFu) { bF = (int)(v & 0xFFu); Tw = (int)(v >> 8); }
        }
        float F    = 100.0f * (float)bF;
        float Ft   = 4.0f * (float)Tw;
        float last = 4.0f * (float)(n_win - 1);
        out[3 * n_win + 0] = F;
        out[3 * n_win + 1] = __fdiv_rn((last - Ft) * 1000.0f, 44100.0f);
    }
}

// ---------------------------------------------------------------------------
// Scan phase 3: parallel fill. One warp per segment replays the exact
// reference emit semantics (cond/emit use PRE-update state) via ballots.
// ---------------------------------------------------------------------------
__global__ void k_fill(int n_win, float* __restrict__ out) {
    const int seg = blockIdx.x;
    const int s0  = seg * SEG;
    const int len = min(SEG, n_win - s0);
    const int lane = threadIdx.x;

    int2 st0 = g_segin[seg];
    float F = 100.0f * (float)st0.x;
    float T = 4.0f * (float)st0.y;

    float* flags = out;
    float* freqs = out + n_win;
    float* durs  = out + 2 * n_win;

    for (int base = 0; base < len; base += 32) {
        int  i     = s0 + base + lane;
        bool valid = (base + lane) < len;
        float t = valid ? 100.0f * (float)g_bins[i] : 0.0f;

        unsigned rem = __ballot_sync(0xffffffffu, valid);
        float myF = 0.f, myT = 0.f;
        bool  myc = false;
        while (rem) {
            bool oob = fabsf(F - t) > F * RELC;
            unsigned bal = __ballot_sync(0xffffffffu, oob) & rem;
            if (!bal) {
                if (rem & (1u << lane)) { myF = F; myT = T; }
                break;
            }
            int e = __ffs(bal) - 1;
            if ((rem & (1u << lane)) && lane <= e) {
                myF = F; myT = T; myc = (lane == e);
            }
            F = __shfl_sync(0xffffffffu, t, e);
            T = 4.0f * (float)(s0 + base + e);
            unsigned below = (e == 31) ? 0xffffffffu : ((1u << (e + 1)) - 1u);
            rem &= ~below;
        }
        if (valid) {
            flags[i] = myc ? 1.0f : 0.0f;
            freqs[i] = myF;
            durs[i]  = __fdiv_rn(((float)(4 * i) - myT) * 1000.0f, 44100.0f);
        }
    }
}

// ---------------------------------------------------------------------------
extern "C" void kernel_launch(void* const* d_in, const int* in_sizes, int n_in,
                              void* d_out, int out_size) {
    const float* x = (const float*)d_in[0];
    int n     = in_sizes[0];
    int n_win = (n - WIN + HOP - 1) / HOP;
    if (n_win > MAXWIN) n_win = MAXWIN;   // safety cap (fixed input: 249890)
    int nblk = (n_win + CWIN - 1) / CWIN;
    int nseg = (n_win + SEG - 1) / SEG;
    float* out = (float*)d_out;

    size_t walk_smem = (size_t)nseg * NBINS * sizeof(unsigned);  // ~108.7 KB
    static bool attr_done = false;
    if (!attr_done) {
        cudaFuncSetAttribute(k_walk, cudaFuncAttributeMaxDynamicSharedMemorySize,
                             (int)(116 * 1024));
        attr_done = true;
    }

    k_init_tables<<<1, 448>>>();
    k_dft<<<nblk, 224>>>(x, n_win);
    k_segmaps<<<nseg, 256>>>(n_win);
    k_walk<<<1, 1024, walk_smem>>>(n_win, nseg, out);
    k_fill<<<nseg, 32>>>(n_win, out);
}

// round 11
// speedup vs baseline: 2.1638x; 1.1492x over previous
#include <cuda_runtime.h>
#include <stdint.h>

#define WIN   442
#define NBINS 221
#define HOP   4
#define RELC  0.0594f
#define CWIN  432           // 579 blocks -> ONE wave at 4 blocks/SM
#define BATW  36            // windows per argmax batch (432 = 12 * 36)
#define RS    229           // mags row stride (229 mod 32 = 5, conflict-free)
#define SEG   2048          // windows per scan segment
#define MAXWIN 262144
#define MAXSEG (MAXWIN / SEG)
#define CSCSZ (WIN + (WIN >> 4) + 1)   // skewed LUT size (442 + 27)

typedef unsigned long long u64;

__device__ u64   g_csc[WIN];                 // packed (cos, -sin)
__device__ int   g_bins[MAXWIN];
__device__ __align__(16) unsigned g_mapsP[MAXSEG * NBINS];
__device__ int2  g_segin[MAXSEG];

// ---------------------------------------------------------------------------
// Twiddle LUT: csc[m] = (cos(2pi m/442), -sin(2pi m/442)) packed, fp32.
// ---------------------------------------------------------------------------
__global__ void k_init_tables() {
    int m = threadIdx.x;
    if (m < WIN) {
        double ang = (2.0 * 3.141592653589793238462643 * (double)m) / (double)WIN;
        float c = (float)cos(ang), s = (float)sin(ang);
        g_csc[m] = ((u64)__float_as_uint(-s) << 32) | (u64)__float_as_uint(c);
    }
}

// ---------------------------------------------------------------------------
// Packed f32x2 primitives (lane0 = re, lane1 = im). Componentwise RN.
// ---------------------------------------------------------------------------
__device__ __forceinline__ u64 pk2(float lo, float hi) {
    u64 r; asm("mov.b64 %0, {%1, %2};" : "=l"(r) : "f"(lo), "f"(hi)); return r;
}
__device__ __forceinline__ void upk2(u64 v, float& lo, float& hi) {
    asm("mov.b64 {%0, %1}, %2;" : "=f"(lo), "=f"(hi) : "l"(v));
}
__device__ __forceinline__ u64 add2(u64 a, u64 b) {
    u64 r; asm("add.rn.f32x2 %0, %1, %2;" : "=l"(r) : "l"(a), "l"(b)); return r;
}
__device__ __forceinline__ u64 neg2(u64 a) { return a ^ 0x8000000080000000ull; }

// Kahan with negated compensation NC = -C (used only once per batch).
__device__ __forceinline__ void kaddn(u64& S, u64& NC, u64 P) {
    u64 y = add2(P, NC);
    u64 t = add2(S, y);
    NC = add2(add2(S, neg2(t)), y);
    S = t;
}

// skewed LUT index: breaks power-of-2-stride bank conflicts on the 8B table
__device__ __forceinline__ int sk(int m) { return m + (m >> 4); }

// ---------------------------------------------------------------------------
// DFT + argmax, rotation-free + twiddle-factored + hierarchical accumulation.
// One block = 432 windows, thread -> bin kk = min(tid, 220).
//   Y_w = W4^{-w} X_w = Ybase (Kahan, folded per batch) + S_loc (plain f32x2
//   running sum of this batch's deltas; adds round at the SMALL delta-partial
//   magnitude, so noise stays ~1e-7 relative).
// Slide: S_loc += T0_w * (d0 + d1 E1 + d2 E2 + d3 E3), with T0_w = csc[idx0]
// (shared with the magnitude rotation), E_j per-thread register constants,
// and d_j PRECOMPUTED per window into smem (k-independent, broadcast LDS.128).
// Magnitude: X_w = conj(T0_w) * (Ybase + NC + S_loc), non-accumulating.
// Argmax batched: mags -> smem, 216 threads reduce (window, bin-sixth) with
// strict > ascending (ties -> lowest bin = jnp.argmax), u64-key merge.
// ---------------------------------------------------------------------------
__global__ __launch_bounds__(224, 4) void k_dft(const float* __restrict__ x, int n_win) {
    __shared__ __align__(16) float xs[WIN + 4 * CWIN];   // 2170 floats
    __shared__ __align__(16) float ds[4 * CWIN];         // per-window deltas
    __shared__ u64   csc[CSCSZ];
    __shared__ float mags[BATW * RS];                    // 36 x 229
    __shared__ u64   pkeys[BATW * 7];

    const int tid = threadIdx.x;
    const int w0  = blockIdx.x * CWIN;
    const int nc  = min(CWIN, n_win - w0);
    const int s0  = w0 * HOP;
    const int L   = 4 * nc + 438;

    for (int i = tid; i < L; i += blockDim.x) xs[i] = x[s0 + i];
    for (int i = tid; i < WIN; i += blockDim.x) csc[sk(i)] = g_csc[i];
    __syncthreads();

    // precompute deltas: ds[p] = xs[p+442] - xs[p], p in [0, 4*(nc-1))
    for (int i = tid; i < 4 * (nc - 1); i += blockDim.x)
        ds[i] = __fsub_rn(xs[i + 442], xs[i]);

    const int kk = min(tid, NBINS - 1);       // clamp: tail lanes dup bin 220
    const int step = (4 * kk) % WIN;

    // per-thread twiddle constants E_j = (cos(j th k), -sin(j th k))
    float e1r, e1i, e2r, e2i, e3r, e3i;
    upk2(csc[sk(kk)], e1r, e1i);
    upk2(csc[sk((2 * kk) % WIN)], e2r, e2i);
    upk2(csc[sk((3 * kk) % WIN)], e3r, e3i);

    int idx0 = 0;
    u64 YB = 0ull, NC = 0ull;                 // batch-level Kahan base
    u64 SL = 0ull;                            // within-batch plain sum

    // ---- direct DFT of window 0 (into YB via Kahan; groups of 4 taps) ----
    #pragma unroll 2
    for (int g = 0; g < 110; g++) {
        const float4 xv = *(const float4*)&xs[4 * g];
        float tc, nsn;  upk2(csc[sk(idx0)], tc, nsn);
        float Zr = __fmaf_rn(xv.w, e3r, __fmaf_rn(xv.z, e2r, __fmaf_rn(xv.y, e1r, xv.x)));
        float Zi = __fmaf_rn(xv.w, e3i, __fmaf_rn(xv.z, e2i, __fmul_rn(xv.y, e1i)));
        float Dre = __fmaf_rn(-Zi, nsn, __fmul_rn(Zr, tc));
        float Dim = __fmaf_rn( Zi, tc,  __fmul_rn(Zr, nsn));
        kaddn(YB, NC, pk2(Dre, Dim));
        idx0 += step; if (idx0 >= WIN) idx0 -= WIN;
    }
    {   // tail taps n = 440, 441 (idx0 = 440k mod 442 here)
        float tc, nsn;  upk2(csc[sk(idx0)], tc, nsn);
        float x0 = xs[440], x1 = xs[441];
        float Zr = __fmaf_rn(x1, e1r, x0);
        float Zi = __fmul_rn(x1, e1i);
        float Dre = __fmaf_rn(-Zi, nsn, __fmul_rn(Zr, tc));
        float Dim = __fmaf_rn( Zi, tc,  __fmul_rn(Zr, nsn));
        kaddn(YB, NC, pk2(Dre, Dim));
    }
    idx0 = 0;                                  // window-0 frame for slides
    __syncthreads();                           // ds ready for all threads

    for (int b0 = 0; b0 < nc; b0 += BATW) {
        const int bw = min(BATW, nc - b0);

        // ---- phase 1: mags for bw windows, sliding S_loc between them ----
        float* mrow = &mags[tid];
        for (int w = b0; w < b0 + bw; w++) {
            float tc, nsn;  upk2(csc[sk(idx0)], tc, nsn);   // T0_w

            u64 Yc = add2(add2(YB, NC), SL);
            float yr, yi;  upk2(Yc, yr, yi);
            float xr = __fmaf_rn(yi, nsn, __fmul_rn(yr, tc));
            float xi = __fmaf_rn(yi, tc, -__fmul_rn(yr, nsn));
            mrow[(w - b0) * RS] = __fadd_rn(fabsf(xr), fabsf(xi));

            if (w + 1 < nc) {
                const float4 d = *(const float4*)&ds[4 * w];
                float Zr = __fmaf_rn(d.w, e3r, __fmaf_rn(d.z, e2r, __fmaf_rn(d.y, e1r, d.x)));
                float Zi = __fmaf_rn(d.w, e3i, __fmaf_rn(d.z, e2i, __fmul_rn(d.y, e1i)));
                float Dre = __fmaf_rn(-Zi, nsn, __fmul_rn(Zr, tc));
                float Dim = __fmaf_rn( Zi, tc,  __fmul_rn(Zr, nsn));
                SL = add2(SL, pk2(Dre, Dim));
                idx0 += step; if (idx0 >= WIN) idx0 -= WIN;
            }
        }
        // fold batch total into the Kahan base; reset local sum
        kaddn(YB, NC, SL);
        SL = 0ull;
        __syncthreads();

        // ---- phase 2: per-window partial argmax over bin sixths ----
        {
            const int win  = tid % BATW;
            const int part = tid / BATW;         // 0..5 used (216 threads)
            if (part < 6 && win < bw) {
                const int kbeg = part * 37;
                const int kend = min(kbeg + 37, NBINS);
                const float* row = &mags[win * RS];
                float best = row[kbeg];
                int   bbin = kbeg;
                for (int kx = kbeg + 1; kx < kend; kx++) {
                    float v = row[kx];
                    if (v > best) { best = v; bbin = kx; }   // ties -> lower
                }
                pkeys[win * 7 + part] =
                    (((u64)__float_as_uint(best)) << 32)
                    | (u64)(0xFFFFFFFFu - (unsigned)bbin);
            }
        }
        __syncthreads();

        // ---- merge 6 partials per window (packed-key max: ties -> low bin)
        if (tid < bw) {
            u64 m = pkeys[tid * 7];
            #pragma unroll
            for (int j = 1; j < 6; j++) {
                u64 v = pkeys[tid * 7 + j];
                if (v > m) m = v;
            }
            g_bins[w0 + b0 + tid] = (int)(0xFFFFFFFFu - (unsigned)(m & 0xFFFFFFFFull));
        }
        __syncthreads();
    }
}

// ---------------------------------------------------------------------------
// Scan phase 1: per-segment transition maps, written PACKED:
// (global_reset_time << 8) | bin, sentinel 0xFFFFFFFF = state survives.
// ---------------------------------------------------------------------------
__global__ void k_segmaps(int n_win) {
    __shared__ int   sb[SEG];
    __shared__ short sj[SEG];
    const int seg = blockIdx.x;
    const int s0  = seg * SEG;
    const int len = min(SEG, n_win - s0);

    for (int i = threadIdx.x; i < SEG; i += blockDim.x)
        sb[i] = (i < len) ? g_bins[s0 + i] : 0;
    __syncthreads();

    for (int p = threadIdx.x; p < len; p += blockDim.x) {
        float F   = 100.0f * (float)sb[p];
        float thr = F * RELC;
        int j = p + 1;
        while (j < len && fabsf(F - 100.0f * (float)sb[j]) <= thr) j++;
        sj[p] = (short)((j < len) ? j : p);      // self-loop == terminal
    }
    __syncthreads();

    for (int r = 0; r < 11; r++) {               // log2(2048) rounds
        for (int p = threadIdx.x; p < len; p += blockDim.x)
            sj[p] = sj[sj[p]];
        __syncthreads();
    }

    for (int f = threadIdx.x; f < NBINS; f += blockDim.x) {
        float F   = 100.0f * (float)f;
        float thr = F * RELC;
        int j = 0;
        while (j < len && fabsf(F - 100.0f * (float)sb[j]) <= thr) j++;
        unsigned v;
        if (j >= len) v = 0xFFFFFFFFu;
        else { int term = sj[j]; v = (((unsigned)(s0 + term)) << 8) | (unsigned)sb[term]; }
        g_mapsP[seg * NBINS + f] = v;
    }
}

// ---------------------------------------------------------------------------
// Scan phase 2: bulk-load packed maps (108 KB) with wide uint4 loads and
// 1024 threads (deep MLP), then thread 0 walks the chain in shared memory.
// ---------------------------------------------------------------------------
__global__ void k_walk(int n_win, int nseg, float* __restrict__ out) {
    extern __shared__ unsigned sm[];
    const int tot  = nseg * NBINS;
    const int tot4 = tot >> 2;
    const uint4* src4 = (const uint4*)g_mapsP;
    uint4* dst4 = (uint4*)sm;
    for (int i = threadIdx.x; i < tot4; i += blockDim.x) dst4[i] = src4[i];
    for (int i = (tot4 << 2) + threadIdx.x; i < tot; i += blockDim.x) sm[i] = g_mapsP[i];
    __syncthreads();

    if (threadIdx.x == 0) {
        int bF = 0, Tw = 0;
        for (int s = 0; s < nseg; s++) {
            g_segin[s] = make_int2(bF, Tw);
            unsigned v = sm[s * NBINS + bF];
            if (v != 0xFFFFFFFFu) { bF = (int)(v & 0xFFu); Tw = (int)(v >> 8); }
        }
        float F    = 100.0f * (float)bF;
        float Ft   = 4.0f * (float)Tw;
        float last = 4.0f * (float)(n_win - 1);
        out[3 * n_win + 0] = F;
        out[3 * n_win + 1] = __fdiv_rn((last - Ft) * 1000.0f, 44100.0f);
    }
}

// ---------------------------------------------------------------------------
// Scan phase 3: parallel fill. One warp per segment replays the exact
// reference emit semantics (cond/emit use PRE-update state) via ballots.
// ---------------------------------------------------------------------------
__global__ void k_fill(int n_win, float* __restrict__ out) {
    const int seg = blockIdx.x;
    const int s0  = seg * SEG;
    const int len = min(SEG, n_win - s0);
    const int lane = threadIdx.x;

    int2 st0 = g_segin[seg];
    float F = 100.0f * (float)st0.x;
    float T = 4.0f * (float)st0.y;

    float* flags = out;
    float* freqs = out + n_win;
    float* durs  = out + 2 * n_win;

    for (int base = 0; base < len; base += 32) {
        int  i     = s0 + base + lane;
        bool valid = (base + lane) < len;
        float t = valid ? 100.0f * (float)g_bins[i] : 0.0f;

        unsigned rem = __ballot_sync(0xffffffffu, valid);
        float myF = 0.f, myT = 0.f;
        bool  myc = false;
        while (rem) {
            bool oob = fabsf(F - t) > F * RELC;
            unsigned bal = __ballot_sync(0xffffffffu, oob) & rem;
            if (!bal) {
                if (rem & (1u << lane)) { myF = F; myT = T; }
                break;
            }
            int e = __ffs(bal) - 1;
            if ((rem & (1u << lane)) && lane <= e) {
                myF = F; myT = T; myc = (lane == e);
            }
            F = __shfl_sync(0xffffffffu, t, e);
            T = 4.0f * (float)(s0 + base + e);
            unsigned below = (e == 31) ? 0xffffffffu : ((1u << (e + 1)) - 1u);
            rem &= ~below;
        }
        if (valid) {
            flags[i] = myc ? 1.0f : 0.0f;
            freqs[i] = myF;
            durs[i]  = __fdiv_rn(((float)(4 * i) - myT) * 1000.0f, 44100.0f);
        }
    }
}

// ---------------------------------------------------------------------------
extern "C" void kernel_launch(void* const* d_in, const int* in_sizes, int n_in,
                              void* d_out, int out_size) {
    const float* x = (const float*)d_in[0];
    int n     = in_sizes[0];
    int n_win = (n - WIN + HOP - 1) / HOP;
    if (n_win > MAXWIN) n_win = MAXWIN;   // safety cap (fixed input: 249890)
    int nblk = (n_win + CWIN - 1) / CWIN;
    int nseg = (n_win + SEG - 1) / SEG;
    float* out = (float*)d_out;

    size_t walk_smem = (size_t)nseg * NBINS * sizeof(unsigned);  // ~108.7 KB
    static bool attr_done = false;
    if (!attr_done) {
        cudaFuncSetAttribute(k_walk, cudaFuncAttributeMaxDynamicSharedMemorySize,
                             (int)(116 * 1024));
        attr_done = true;
    }

    k_init_tables<<<1, 448>>>();
    k_dft<<<nblk, 224>>>(x, n_win);
    k_segmaps<<<nseg, 256>>>(n_win);
    k_walk<<<1, 1024, walk_smem>>>(n_win, nseg, out);
    k_fill<<<nseg, 32>>>(n_win, out);
}